// round 14
// baseline (speedup 1.0000x reference)
#include <cuda_runtime.h>
#include <math.h>

#define MAXN 20000
#define MAXE 320000

typedef unsigned long long ull;
typedef ulonglong2 ull2;

// ---------------- scratch (device globals) ---------------------------------
__device__ float g_pre[MAXN * 256];
__device__ float g_tmp[MAXN * 256];
__device__ float g_xg [MAXN * 256];
__device__ float g_acc[MAXN * 256];
__device__ float g_dummy[MAXN * 256];   // probe sink
__device__ float g_h1a[MAXE * 32];
__device__ float g_h1l[MAXE * 32];
__device__ float g_WfT[320 * 32];
__device__ float g_WlT[320 * 32];
__device__ float g_Wf1T[32 * 72];
__device__ float g_Wl1T[32 * 136];
__device__ ull   g_eW[3 * 4096];

__device__ __forceinline__ float sspf(float x) {
    float sp = (x > 15.f) ? x : log1pf(expf(x));
    return sp - 0.69314718055994531f;
}
__device__ __forceinline__ float siluf(float x) {
    return x / (1.f + expf(-x));
}
__device__ __forceinline__ ull pack2(float a, float b) {
    ull r; asm("mov.b64 %0, {%1, %2};" : "=l"(r) : "f"(a), "f"(b)); return r;
}
__device__ __forceinline__ void fma2(ull& d, ull a, ull b) {
    asm("fma.rn.f32x2 %0, %1, %2, %0;" : "+l"(d) : "l"(a), "l"(b));
}
__device__ __forceinline__ void unpack2(ull v, float& lo, float& hi) {
    asm("mov.b64 {%0, %1}, %2;" : "=f"(lo), "=f"(hi) : "l"(v));
}
__device__ __forceinline__ unsigned tf32r(float x) {
    unsigned r; asm("cvt.rna.tf32.f32 %0, %1;" : "=r"(r) : "f"(x)); return r;
}
__device__ __forceinline__ float tf32f(float x) {
    return __uint_as_float(tf32r(x));
}
__device__ __forceinline__ void mma_tf32(float* d, const unsigned* a, const unsigned* b) {
    asm("mma.sync.aligned.m16n8k8.row.col.f32.tf32.tf32.f32 "
        "{%0,%1,%2,%3}, {%4,%5,%6,%7}, {%8,%9}, {%0,%1,%2,%3};"
        : "+f"(d[0]), "+f"(d[1]), "+f"(d[2]), "+f"(d[3])
        : "r"(a[0]), "r"(a[1]), "r"(a[2]), "r"(a[3]), "r"(b[0]), "r"(b[1]));
}
__device__ __forceinline__ void cpa16(unsigned dst, const float* src, int sz) {
    asm volatile("cp.async.cg.shared.global [%0], [%1], 16, %2;"
                 :: "r"(dst), "l"(src), "r"(sz) : "memory");
}

// ---------------- weight prep ----------------------------------------------
__global__ void prep_kernel(const float* __restrict__ Wf2,
                            const float* __restrict__ Wl2,
                            const float* __restrict__ Wl1,
                            const float* __restrict__ Wpre0,
                            const float* __restrict__ Wpre1,
                            const float* __restrict__ Wn0,
                            const float* __restrict__ Wn1,
                            const float* __restrict__ Wo0,
                            const float* __restrict__ Wo1,
                            const float* __restrict__ Wf1) {
    int i = blockIdx.x * 256 + threadIdx.x;
    const float is32 = 0.17677669529663687f;
    const float r192 = 0.07216878364870323f;
    if (i < 320 * 32) {
        int c = i >> 5, k = i & 31;
        g_WfT[i] = tf32f(Wf2[k * 320 + c] * is32);
        g_WlT[i] = tf32f(Wl2[k * 320 + c] * is32);
    }
    if (i < 3 * 4096) {
        int p = i >> 12, r = i & 4095;
        const float* w0 = (p == 0) ? Wpre0 : (p == 1) ? Wn0 : Wo0;
        const float* w1 = (p == 0) ? Wpre1 : (p == 1) ? Wn1 : Wo1;
        g_eW[i] = pack2(w0[r] * 0.125f, w1[r] * 0.125f);
    }
    if (i < 2048) {
        int c = i >> 6, k = i & 63;
        g_Wf1T[c * 72 + k] = tf32f(Wf1[k * 32 + c] * 0.125f);
    }
    if (i < 4096) {
        int c = i >> 7, k = i & 127;
        float v = (k < 64) ? (Wl1[k * 32 + c] + Wl1[(64 + k) * 32 + c]) * r192
                           : Wl1[(64 + k) * 32 + c] * r192;
        g_Wl1T[c * 136 + k] = tf32f(v);
    }
}

// ---------------- e3_linear: 16 nodes/block --------------------------------
template<int IL, int OL, int OL2>
__global__ void e3_kernel(const float* __restrict__ in,
                          int widx,
                          const float* __restrict__ b0,
                          float* __restrict__ out,
                          float* __restrict__ out2, int nN) {
    extern __shared__ float sme3[];
    ull*   Wp  = (ull*)sme3;
    float* ins = sme3 + 8192;
    float* b0s = sme3 + 8192 + 4096;
    int tid = threadIdx.x;
    {
        const ull2* src = (const ull2*)(g_eW + widx * 4096);
        ull2* dst = (ull2*)Wp;
        for (int i = tid; i < 2048; i += 256) dst[i] = src[i];
    }
    if (tid < 64) b0s[tid] = b0[tid];
    int n0 = blockIdx.x * 16;
    if (IL == 0) {
        for (int i = tid; i < 256; i += 256) {
            int nl = i >> 4, g4 = i & 15;
            int u0 = g4 * 4;
            int n = n0 + nl;
            float4 a = make_float4(0.f,0.f,0.f,0.f), b = a, cc = a, dd = a;
            if (n < nN) {
                const float* xr = in + n * 256;
                a  = *(const float4*)(xr + u0);
                const float4* vp = (const float4*)(xr + 64 + u0 * 3);
                b = vp[0]; cc = vp[1]; dd = vp[2];
            }
            float4* q = (float4*)(ins + nl * 256 + u0 * 4);
            q[0] = make_float4(a.x, b.x, b.y, b.z);
            q[1] = make_float4(a.y, b.w, cc.x, cc.y);
            q[2] = make_float4(a.z, cc.z, cc.w, dd.x);
            q[3] = make_float4(a.w, dd.y, dd.z, dd.w);
        }
    } else {
        for (int i = tid; i < 1024; i += 256) {
            int nl = i >> 6, q = i & 63;
            int n = n0 + nl;
            float4 v = (n < nN) ? ((const float4*)(in + n * 256))[q]
                                : make_float4(0.f, 0.f, 0.f, 0.f);
            ((float4*)(ins + nl * 256))[q] = v;
        }
    }
    __syncthreads();
    int v = tid & 63, g = tid >> 6;
    const float* base = ins + g * 4 * 256;
    ull acc[4][2] = {};
    #pragma unroll 4
    for (int u = 0; u < 64; u++) {
        ull wp = Wp[u * 64 + v];
        float w0, w1; unpack2(wp, w0, w1);
        ull wq = pack2(w1, w1);
        #pragma unroll
        for (int t = 0; t < 4; t++) {
            ull2 q = *(const ull2*)(base + t * 256 + u * 4);
            fma2(acc[t][0], wp, q.x);
            fma2(acc[t][1], wq, q.y);
        }
    }
    float bias = b0s[v];
    float rs[4], r0[4], r1[4], r2[4];
    #pragma unroll
    for (int t = 0; t < 4; t++) {
        unpack2(acc[t][0], rs[t], r0[t]);
        unpack2(acc[t][1], r1[t], r2[t]);
        rs[t] += bias;
    }
    #pragma unroll
    for (int t = 0; t < 4; t++) {
        int n = n0 + g * 4 + t;
        if (n >= nN) continue;
        float4 q = make_float4(rs[t], r0[t], r1[t], r2[t]);
        if (OL == 1) ((float4*)(out + n * 256))[v] = q;
        if (out2 && OL2 == 1) ((float4*)(out2 + n * 256))[v] = q;
    }
    if (OL == 0) {
        __syncthreads();
        #pragma unroll
        for (int t = 0; t < 4; t++) {
            float* row = ins + (g * 4 + t) * 256;
            row[v] = rs[t];
            row[64 + v * 3 + 0] = r0[t];
            row[64 + v * 3 + 1] = r1[t];
            row[64 + v * 3 + 2] = r2[t];
        }
        __syncthreads();
        for (int i = tid; i < 1024; i += 256) {
            int nl = i >> 6, q = i & 63;
            int n = n0 + nl;
            if (n < nN)
                ((float4*)(out + n * 256))[q] = ((float4*)(ins + nl * 256))[q];
        }
    }
}

// ---------------- gate MLP (fp32 f32x2, 64 nodes/block, 512 thr) ------------
__global__ void __launch_bounds__(512, 1)
gate_kernel(const float* __restrict__ x,
            const float* __restrict__ Wg1,
            const float* __restrict__ bg1,
            const float* __restrict__ Wg2,
            const float* __restrict__ bg2,
            float* __restrict__ outb, int nN) {
    extern __shared__ float sm[];
    float* W1s = sm;
    float* W2s = sm + 16384;
    float* f0t = sm + 32768;
    float* hst = sm + 41472;
    int tid = threadIdx.x;
    for (int i = tid; i < 4096; i += 512) {
        ((float4*)W1s)[i] = ((const float4*)Wg1)[i];
        ((float4*)W2s)[i] = ((const float4*)Wg2)[i];
    }
    int n0 = blockIdx.x * 64;
    for (int i = tid; i < 8192; i += 512) {
        int nl = i & 63, j = i >> 6;
        int n = n0 + nl;
        float val = 0.f;
        if (n < nN) {
            const float* xr = x + n * 256;
            if (j < 64) val = xr[j];
            else {
                int u = j - 64;
                float v0 = xr[64 + u * 3], v1 = xr[64 + u * 3 + 1], v2 = xr[64 + u * 3 + 2];
                val = sqrtf(v0 * v0 + v1 * v1 + v2 * v2 + 1e-12f);
            }
        }
        f0t[j * 68 + nl] = val;
    }
    __syncthreads();
    int j = tid & 127, quarter = tid >> 7;
    int nb = quarter * 16;
    {
        ull a[8] = {};
        #pragma unroll 4
        for (int k = 0; k < 128; k++) {
            float w = W1s[k * 128 + j];
            ull wp = pack2(w, w);
            const ull2* f = (const ull2*)&f0t[k * 68 + nb];
            #pragma unroll
            for (int q = 0; q < 4; q++) {
                ull2 v = f[q];
                fma2(a[q * 2], wp, v.x);
                fma2(a[q * 2 + 1], wp, v.y);
            }
        }
        float b = bg1[j];
        #pragma unroll
        for (int q = 0; q < 8; q++) {
            float lo, hi; unpack2(a[q], lo, hi);
            hst[j * 68 + nb + q * 2]     = siluf(lo + b);
            hst[j * 68 + nb + q * 2 + 1] = siluf(hi + b);
        }
    }
    __syncthreads();
    float g[16];
    {
        ull a[8] = {};
        #pragma unroll 4
        for (int k = 0; k < 128; k++) {
            float w = W2s[k * 128 + j];
            ull wp = pack2(w, w);
            const ull2* h = (const ull2*)&hst[k * 68 + nb];
            #pragma unroll
            for (int q = 0; q < 4; q++) {
                ull2 v = h[q];
                fma2(a[q * 2], wp, v.x);
                fma2(a[q * 2 + 1], wp, v.y);
            }
        }
        float b = bg2[j];
        #pragma unroll
        for (int q = 0; q < 8; q++) {
            unpack2(a[q], g[q * 2], g[q * 2 + 1]);
            g[q * 2] += b; g[q * 2 + 1] += b;
        }
    }
    #pragma unroll
    for (int p = 0; p < 16; p++) f0t[(nb + p) * 128 + j] = g[p];
    __syncthreads();
    for (int q2 = tid; q2 < 4096; q2 += 512) {
        int nl = q2 >> 6, u = q2 & 63;
        int n = n0 + nl;
        if (n >= nN) continue;
        float gs = f0t[nl * 128 + u];
        float gv = f0t[nl * 128 + 64 + u];
        const float* xr = x + n * 256 + 64 + u * 3;
        ((float4*)(outb + n * 256))[u] = make_float4(gs, xr[0] * gv, xr[1] * gv, xr[2] * gv);
    }
}

// ---------------- h1a: tf32 MMA (outputs tf32-rounded) ----------------------
__global__ void __launch_bounds__(256, 2)
h1a_mma(const float* __restrict__ attr, float* __restrict__ h1a, int nE) {
    extern __shared__ float sa[];
    float* at = sa;
    float* BT = sa + 8704;
    int tid = threadIdx.x;
    int e0 = blockIdx.x * 128;
    for (int i = tid; i < 576; i += 256)
        ((float4*)BT)[i] = ((const float4*)g_Wf1T)[i];
    for (int i = tid; i < 2048; i += 256) {
        int el = i >> 4, u0 = (i & 15) * 4;
        int e = e0 + el;
        float4 a4 = (e < nE) ? *(const float4*)&attr[e * 64 + u0]
                             : make_float4(0.f, 0.f, 0.f, 0.f);
        *(float4*)&at[el * 68 + u0] =
            make_float4(tf32f(a4.x), tf32f(a4.y), tf32f(a4.z), tf32f(a4.w));
    }
    __syncthreads();
    int lane = tid & 31, w = tid >> 5;
    int group = lane >> 2, tig = lane & 3;
    int m0 = w * 16;
    int rowA = (m0 + group) * 68;
    float acc[4][4] = {};
    #pragma unroll 1
    for (int ks = 0; ks < 8; ks++) {
        int c = ks * 8 + tig;
        unsigned a[4];
        a[0] = __float_as_uint(at[rowA + c]);
        a[1] = __float_as_uint(at[rowA + 544 + c]);
        a[2] = __float_as_uint(at[rowA + c + 4]);
        a[3] = __float_as_uint(at[rowA + 544 + c + 4]);
        #pragma unroll
        for (int j = 0; j < 4; j++) {
            unsigned b[2];
            int br = (j * 8 + group) * 72 + ks * 8 + tig;
            b[0] = __float_as_uint(BT[br]);
            b[1] = __float_as_uint(BT[br + 4]);
            mma_tf32(acc[j], a, b);
        }
    }
    int eA = e0 + m0 + group, eB = eA + 8;
    #pragma unroll
    for (int j = 0; j < 4; j++) {
        int c0 = j * 8 + 2 * tig;
        if (eA < nE)
            *(float2*)&h1a[eA * 32 + c0] =
                make_float2(tf32f(sspf(acc[j][0])), tf32f(sspf(acc[j][1])));
        if (eB < nE)
            *(float2*)&h1a[eB * 32 + c0] =
                make_float2(tf32f(sspf(acc[j][2])), tf32f(sspf(acc[j][3])));
    }
}

// ---------------- h1l: tf32 MMA (outputs tf32-rounded) ----------------------
__global__ void __launch_bounds__(256, 2)
h1l_mma(const int* __restrict__ ei, const float* __restrict__ pre,
        float* __restrict__ h1l, int nE, int Etot) {
    extern __shared__ float sl[];
    float* st = sl;
    float* BT = sl + 16896;
    int*   idx = (int*)(sl + 21248);
    int tid = threadIdx.x;
    int e0 = blockIdx.x * 128;
    for (int i = tid; i < 1088; i += 256)
        ((float4*)BT)[i] = ((const float4*)g_Wl1T)[i];
    if (tid < 128) {
        int e = e0 + tid;
        bool v = (e < nE);
        idx[tid]       = v ? ei[e] : 0;
        idx[128 + tid] = v ? ei[Etot + e] : 0;
    }
    __syncthreads();
    for (int i = tid; i < 8192; i += 256) {
        int el = i >> 6, u = i & 63;
        int d = idx[el], s = idx[128 + el];
        float4 qd = *(const float4*)&pre[d * 256 + u * 4];
        float4 qs = *(const float4*)&pre[s * 256 + u * 4];
        st[el * 132 + u] = tf32f(qd.x);
        st[el * 132 + 64 + u] =
            tf32f((qd.y * qs.y + qd.z * qs.z + qd.w * qs.w) * (1.f / 3.f));
    }
    __syncthreads();
    int lane = tid & 31, w = tid >> 5;
    int group = lane >> 2, tig = lane & 3;
    int m0 = w * 16;
    int rowA = (m0 + group) * 132;
    float acc[4][4] = {};
    #pragma unroll 1
    for (int ks = 0; ks < 16; ks++) {
        int c = ks * 8 + tig;
        unsigned a[4];
        a[0] = __float_as_uint(st[rowA + c]);
        a[1] = __float_as_uint(st[rowA + 1056 + c]);
        a[2] = __float_as_uint(st[rowA + c + 4]);
        a[3] = __float_as_uint(st[rowA + 1056 + c + 4]);
        #pragma unroll
        for (int j = 0; j < 4; j++) {
            unsigned b[2];
            int br = (j * 8 + group) * 136 + ks * 8 + tig;
            b[0] = __float_as_uint(BT[br]);
            b[1] = __float_as_uint(BT[br + 4]);
            mma_tf32(acc[j], a, b);
        }
    }
    int eA = e0 + m0 + group, eB = eA + 8;
    #pragma unroll
    for (int j = 0; j < 4; j++) {
        int c0 = j * 8 + 2 * tig;
        if (eA < nE)
            *(float2*)&h1l[eA * 32 + c0] =
                make_float2(tf32f(sspf(acc[j][0])), tf32f(sspf(acc[j][1])));
        if (eB < nE)
            *(float2*)&h1l[eB * 32 + c0] =
                make_float2(tf32f(sspf(acc[j][2])), tf32f(sspf(acc[j][3])));
    }
}

// ---------------- fused edge kernel: PERSISTENT + cp.async pipeline ---------
#define TE 64
#define HRS 36
#define WSS 324
#define EDGE_BLOCKS 296
__global__ void __launch_bounds__(320, 2)
edge_kernel(const int* __restrict__ ei,
            const float* __restrict__ sh,
            const float* __restrict__ h1a,
            const float* __restrict__ h1l,
            const float* __restrict__ xg,
            float* __restrict__ acc, int nE, int Etot) {
    extern __shared__ float sm[];
    float* hA  = sm;
    float* hB  = sm + 2304;
    float* ws  = sm + 4608;
    float* WlS = sm + 14976;
    float* shs = sm + 26496;
    int*   idxs = (int*)(sm + 26752);
    int tid = threadIdx.x;
    int lane = tid & 31, wrp = tid >> 5;
    int group = lane >> 2, tig = lane & 3;

    unsigned bf[4][4][2];
    #pragma unroll
    for (int j = 0; j < 4; j++) {
        int n0 = (wrp * 4 + j) * 8;
        #pragma unroll
        for (int ks = 0; ks < 4; ks++) {
            bf[j][ks][0] = __float_as_uint(g_WfT[(n0 + group) * 32 + ks * 8 + tig]);
            bf[j][ks][1] = __float_as_uint(g_WfT[(n0 + group) * 32 + ks * 8 + tig + 4]);
        }
    }
    for (int i = tid; i < 10240; i += 320) {
        int col = i >> 5, k = i & 31;
        WlS[col * 36 + k] = g_WlT[col * 32 + k];
    }

    unsigned hA_s = (unsigned)__cvta_generic_to_shared(hA);
    unsigned hB_s = (unsigned)__cvta_generic_to_shared(hB);

    const float PW_S = 0.44721359549995793f;
    const float PW_V = 0.77459666924148337f;
    const float IS3  = 0.57735026918962576f;
    const float IS2  = 0.70710678118654752f;

    int t = tid - 256;
    int psrc = 0, pdst = -1;
    float4 psh = make_float4(0.f, 0.f, 0.f, 0.f);

    {
        int e0 = blockIdx.x * TE;
        if (t >= 0) {
            int e = e0 + t;
            bool v = (e < nE);
            pdst = v ? ei[e] : -1;
            psrc = v ? ei[Etot + e] : 0;
            psh  = v ? *(const float4*)&sh[e * 4] : make_float4(0.f, 0.f, 0.f, 0.f);
            const float* sa = h1a + (v ? e : 0) * 32;
            const float* sb = h1l + (v ? e : 0) * 32;
            int sz = v ? 16 : 0;
            #pragma unroll
            for (int c = 0; c < 8; c++) {
                cpa16(hA_s + t * 144 + c * 16, sa + c * 4, sz);
                cpa16(hB_s + t * 144 + c * 16, sb + c * 4, sz);
            }
        }
        asm volatile("cp.async.commit_group;" ::: "memory");
    }

    int ntiles = (nE + TE - 1) / TE;
    for (int tile = blockIdx.x; tile < ntiles; tile += gridDim.x) {
        if (t >= 0) {
            idxs[t]      = psrc;
            idxs[64 + t] = pdst;
            ((float4*)shs)[t] = psh;
        }
        asm volatile("cp.async.wait_group 0;" ::: "memory");
        __syncthreads();
        int next = tile + gridDim.x;

        #pragma unroll 1
        for (int half = 0; half < 2; half++) {
            #pragma unroll 1
            for (int mm = 0; mm < 2; mm++) {
                int m0 = (half * 2 + mm) * 16;
                int rowA = (m0 + group) * HRS;
                float dA[4][4] = {}, dB[4][4] = {};
                #pragma unroll
                for (int ks = 0; ks < 4; ks++) {
                    int c = ks * 8 + tig;
                    unsigned aA[4], aB[4];
                    aA[0] = __float_as_uint(hA[rowA + c]);
                    aA[1] = __float_as_uint(hA[rowA + 8 * HRS + c]);
                    aA[2] = __float_as_uint(hA[rowA + c + 4]);
                    aA[3] = __float_as_uint(hA[rowA + 8 * HRS + c + 4]);
                    aB[0] = __float_as_uint(hB[rowA + c]);
                    aB[1] = __float_as_uint(hB[rowA + 8 * HRS + c]);
                    aB[2] = __float_as_uint(hB[rowA + c + 4]);
                    aB[3] = __float_as_uint(hB[rowA + 8 * HRS + c + 4]);
                    #pragma unroll
                    for (int j = 0; j < 4; j++) {
                        mma_tf32(dA[j], aA, bf[j][ks]);
                        unsigned bl[2];
                        int br = ((wrp * 4 + j) * 8 + group) * 36 + ks * 8 + tig;
                        bl[0] = __float_as_uint(WlS[br]);
                        bl[1] = __float_as_uint(WlS[br + 4]);
                        mma_tf32(dB[j], aB, bl);
                    }
                }
                int lrow = mm * 16 + group;
                #pragma unroll
                for (int j = 0; j < 4; j++) {
                    int col0 = (wrp * 4 + j) * 8 + 2 * tig;
                    *(float2*)&ws[lrow * WSS + col0] =
                        make_float2(dA[j][0] * dB[j][0], dA[j][1] * dB[j][1]);
                    *(float2*)&ws[(lrow + 8) * WSS + col0] =
                        make_float2(dA[j][2] * dB[j][2], dA[j][3] * dB[j][3]);
                }
            }
            __syncthreads();
            if (half == 1) {
                if (t >= 0 && next < ntiles) {
                    int e = next * TE + t;
                    bool v = (e < nE);
                    pdst = v ? ei[e] : -1;
                    psrc = v ? ei[Etot + e] : 0;
                    psh  = v ? *(const float4*)&sh[e * 4] : make_float4(0.f, 0.f, 0.f, 0.f);
                    const float* sa = h1a + (v ? e : 0) * 32;
                    const float* sb = h1l + (v ? e : 0) * 32;
                    int sz = v ? 16 : 0;
                    #pragma unroll
                    for (int c = 0; c < 8; c++) {
                        cpa16(hA_s + t * 144 + c * 16, sa + c * 4, sz);
                        cpa16(hB_s + t * 144 + c * 16, sb + c * 4, sz);
                    }
                }
                asm volatile("cp.async.commit_group;" ::: "memory");
            }
            // phase 2: all 320 threads over 32 edges x 64 u
            #pragma unroll 2
            for (int it = tid; it < 2048; it += 320) {
                int el = half * 32 + (it >> 6);
                int u = it & 63;
                int d = idxs[64 + el];
                if (d < 0) continue;
                int s = idxs[el];
                float4 q = *(const float4*)&xg[s * 256 + u * 4];
                float es = q.x, ev0 = q.y, ev1 = q.z, ev2 = q.w;
                float4 shq = ((const float4*)shs)[el];
                float s0 = shq.x, s1 = shq.y, s2 = shq.z, s3 = shq.w;
                const float* we = ws + (el - half * 32) * WSS;
                float w0 = we[u], w1 = we[64 + u], w2 = we[128 + u];
                float w3 = we[192 + u], w4 = we[256 + u];
                float dotv = ev0 * s1 + ev1 * s2 + ev2 * s3;
                float c0 = ev1 * s3 - ev2 * s2;
                float c1 = ev2 * s1 - ev0 * s3;
                float c2 = ev0 * s2 - ev1 * s1;
                float outs = PW_S * (w0 * es * s0 + w3 * dotv * IS3);
                float k2 = PW_V * w2 * s0;
                float k4 = PW_V * w4 * IS2;
                float k1 = PW_V * w1 * es;
                float o0 = k1 * s1 + k2 * ev0 + k4 * c0;
                float o1 = k1 * s2 + k2 * ev1 + k4 * c1;
                float o2 = k1 * s3 + k2 * ev2 + k4 * c2;
                float* pa = acc + d * 256 + u * 4;
                asm volatile("red.global.add.v4.f32 [%0], {%1, %2, %3, %4};"
                             :: "l"(pa), "f"(outs), "f"(o0), "f"(o1), "f"(o2) : "memory");
            }
            __syncthreads();
        }
    }
}

// ---------------- launch ----------------------------------------------------
extern "C" void kernel_launch(void* const* d_in, const int* in_sizes, int n_in,
                              void* d_out, int out_size) {
    const float* x     = (const float*)d_in[0];
    const int*   ei    = (const int*)  d_in[1];
    const float* sh    = (const float*)d_in[2];
    const float* attr  = (const float*)d_in[3];
    const float* Wpre0 = (const float*)d_in[4];
    const float* bpre0 = (const float*)d_in[5];
    const float* Wpre1 = (const float*)d_in[6];
    const float* Wg1   = (const float*)d_in[7];
    const float* bg1   = (const float*)d_in[8];
    const float* Wg2   = (const float*)d_in[9];
    const float* bg2   = (const float*)d_in[10];
    const float* Wn0   = (const float*)d_in[11];
    const float* bn0   = (const float*)d_in[12];
    const float* Wn1   = (const float*)d_in[13];
    const float* Wf1   = (const float*)d_in[14];
    const float* Wf2   = (const float*)d_in[15];
    const float* Wl1   = (const float*)d_in[16];
    const float* Wl2   = (const float*)d_in[17];
    const float* Wo0   = (const float*)d_in[18];
    const float* bo0   = (const float*)d_in[19];
    const float* Wo1   = (const float*)d_in[20];

    int N = in_sizes[0] / 256;
    int E = in_sizes[1] / 2;

    float *pre, *tmp, *xgp, *accp, *dum, *h1a, *h1l;
    cudaGetSymbolAddress((void**)&pre,  g_pre);
    cudaGetSymbolAddress((void**)&tmp,  g_tmp);
    cudaGetSymbolAddress((void**)&xgp,  g_xg);
    cudaGetSymbolAddress((void**)&accp, g_acc);
    cudaGetSymbolAddress((void**)&dum,  g_dummy);
    cudaGetSymbolAddress((void**)&h1a,  g_h1a);
    cudaGetSymbolAddress((void**)&h1l,  g_h1l);

    static const int E3_SMEM   = (8192 + 4096 + 64) * 4;
    static const int GATE_SMEM = (16384 * 2 + 8704 * 2) * 4;
    static const int H1A_SMEM  = (8704 + 2304) * 4;
    static const int H1L_SMEM  = (16896 + 4352 + 256) * 4;
    static const int EDGE_SMEM = (2304 * 2 + 10368 + 11520 + 256 + 128) * 4;
    cudaFuncSetAttribute(e3_kernel<0,1,1>, cudaFuncAttributeMaxDynamicSharedMemorySize, E3_SMEM);
    cudaFuncSetAttribute(e3_kernel<1,1,1>, cudaFuncAttributeMaxDynamicSharedMemorySize, E3_SMEM);
    cudaFuncSetAttribute(e3_kernel<1,0,0>, cudaFuncAttributeMaxDynamicSharedMemorySize, E3_SMEM);
    cudaFuncSetAttribute(gate_kernel, cudaFuncAttributeMaxDynamicSharedMemorySize, GATE_SMEM);
    cudaFuncSetAttribute(h1a_mma,  cudaFuncAttributeMaxDynamicSharedMemorySize, H1A_SMEM);
    cudaFuncSetAttribute(h1l_mma,  cudaFuncAttributeMaxDynamicSharedMemorySize, H1L_SMEM);
    cudaFuncSetAttribute(edge_kernel, cudaFuncAttributeMaxDynamicSharedMemorySize, EDGE_SMEM);

    static cudaStream_t s1 = nullptr, s2 = nullptr;
    static cudaEvent_t ev0, evP, ev1, ev2;
    if (!s1) {
        cudaStreamCreateWithFlags(&s1, cudaStreamNonBlocking);
        cudaStreamCreateWithFlags(&s2, cudaStreamNonBlocking);
        cudaEventCreateWithFlags(&ev0, cudaEventDisableTiming);
        cudaEventCreateWithFlags(&evP, cudaEventDisableTiming);
        cudaEventCreateWithFlags(&ev1, cudaEventDisableTiming);
        cudaEventCreateWithFlags(&ev2, cudaEventDisableTiming);
    }
    cudaStream_t d = 0;

    int E_probe = EDGE_BLOCKS * TE;
    if (E_probe > E) E_probe = E;

    // launch 1: gate (s1, parallel)
    cudaEventRecord(ev0, d);
    cudaStreamWaitEvent(s1, ev0, 0);
    cudaStreamWaitEvent(s2, ev0, 0);
    gate_kernel<<<(N + 63) / 64, 512, GATE_SMEM, s1>>>(x, Wg1, bg1, Wg2, bg2, tmp, N);

    // launch 2: prep (default)
    prep_kernel<<<48, 256, 0, d>>>(Wf2, Wl2, Wl1, Wpre0, Wpre1, Wn0, Wn1, Wo0, Wo1, Wf1);
    cudaEventRecord(evP, d);

    // launches 3,4: edge PROBES (s2; deterministic stale reads, dummy sink)
    edge_kernel<<<EDGE_BLOCKS, 320, EDGE_SMEM, s2>>>(ei, sh, h1a, h1l, xgp, dum, E_probe, E);
    edge_kernel<<<EDGE_BLOCKS, 320, EDGE_SMEM, s2>>>(ei, sh, h1a, h1l, xgp, dum, E_probe, E);
    cudaStreamWaitEvent(s2, evP, 0);

    // launch 5: h1a (s2)
    h1a_mma<<<(E + 127) / 128, 256, H1A_SMEM, s2>>>(attr, h1a, E);
    cudaEventRecord(ev2, s2);

    // launches 6,7: e3pre -> h1l (default)
    e3_kernel<0, 1, 1><<<(N + 15) / 16, 256, E3_SMEM, d>>>(x, 0, bpre0, pre, nullptr, N);
    h1l_mma<<<(E + 127) / 128, 256, H1L_SMEM, d>>>(ei, pre, h1l, E, E);

    // launch 8: e3n (s1)
    cudaStreamWaitEvent(s1, evP, 0);
    e3_kernel<1, 1, 1><<<(N + 15) / 16, 256, E3_SMEM, s1>>>(tmp, 1, bn0, xgp, accp, N);
    cudaEventRecord(ev1, s1);

    // join: edge -> final e3
    cudaStreamWaitEvent(d, ev1, 0);
    cudaStreamWaitEvent(d, ev2, 0);
    int ntiles = (E + TE - 1) / TE;
    int eblocks = ntiles < EDGE_BLOCKS ? ntiles : EDGE_BLOCKS;
    edge_kernel<<<eblocks, 320, EDGE_SMEM, d>>>(ei, sh, h1a, h1l, xgp, accp, E, E);
    e3_kernel<1, 0, 0><<<(N + 15) / 16, 256, E3_SMEM, d>>>(accp, 2, bo0, (float*)d_out, nullptr, N);
}

// round 15
// speedup vs baseline: 1.0990x; 1.0990x over previous
#include <cuda_runtime.h>
#include <math.h>

#define MAXN 20000
#define MAXE 320000

typedef unsigned long long ull;
typedef ulonglong2 ull2;

// ---------------- scratch (device globals) ---------------------------------
__device__ float g_pre[MAXN * 256];
__device__ float g_tmp[MAXN * 256];
__device__ float g_xg [MAXN * 256];
__device__ float g_acc[MAXN * 256];
__device__ float g_h1a[MAXE * 32];
__device__ float g_h1l[MAXE * 32];
__device__ float g_WfT[320 * 32];
__device__ float g_WlT[320 * 32];
__device__ float g_Wf1T[32 * 72];
__device__ float g_Wl1T[32 * 136];
__device__ ull   g_eW[3 * 4096];

__device__ __forceinline__ float sspf(float x) {
    float sp = (x > 15.f) ? x : log1pf(expf(x));
    return sp - 0.69314718055994531f;
}
__device__ __forceinline__ float siluf(float x) {
    return x / (1.f + expf(-x));
}
__device__ __forceinline__ ull pack2(float a, float b) {
    ull r; asm("mov.b64 %0, {%1, %2};" : "=l"(r) : "f"(a), "f"(b)); return r;
}
__device__ __forceinline__ void fma2(ull& d, ull a, ull b) {
    asm("fma.rn.f32x2 %0, %1, %2, %0;" : "+l"(d) : "l"(a), "l"(b));
}
__device__ __forceinline__ void unpack2(ull v, float& lo, float& hi) {
    asm("mov.b64 {%0, %1}, %2;" : "=f"(lo), "=f"(hi) : "l"(v));
}
__device__ __forceinline__ unsigned tf32r(float x) {
    unsigned r; asm("cvt.rna.tf32.f32 %0, %1;" : "=r"(r) : "f"(x)); return r;
}
__device__ __forceinline__ float tf32f(float x) {
    return __uint_as_float(tf32r(x));
}
__device__ __forceinline__ void mma_tf32(float* d, const unsigned* a, const unsigned* b) {
    asm("mma.sync.aligned.m16n8k8.row.col.f32.tf32.tf32.f32 "
        "{%0,%1,%2,%3}, {%4,%5,%6,%7}, {%8,%9}, {%0,%1,%2,%3};"
        : "+f"(d[0]), "+f"(d[1]), "+f"(d[2]), "+f"(d[3])
        : "r"(a[0]), "r"(a[1]), "r"(a[2]), "r"(a[3]), "r"(b[0]), "r"(b[1]));
}
__device__ __forceinline__ void cpa16(unsigned dst, const float* src, int sz) {
    asm volatile("cp.async.cg.shared.global [%0], [%1], 16, %2;"
                 :: "r"(dst), "l"(src), "r"(sz) : "memory");
}

// ---------------- weight prep ----------------------------------------------
__global__ void prep_kernel(const float* __restrict__ Wf2,
                            const float* __restrict__ Wl2,
                            const float* __restrict__ Wl1,
                            const float* __restrict__ Wpre0,
                            const float* __restrict__ Wpre1,
                            const float* __restrict__ Wn0,
                            const float* __restrict__ Wn1,
                            const float* __restrict__ Wo0,
                            const float* __restrict__ Wo1,
                            const float* __restrict__ Wf1) {
    int i = blockIdx.x * 256 + threadIdx.x;
    const float is32 = 0.17677669529663687f;
    const float r192 = 0.07216878364870323f;
    if (i < 320 * 32) {
        int c = i >> 5, k = i & 31;
        g_WfT[i] = tf32f(Wf2[k * 320 + c] * is32);
        g_WlT[i] = tf32f(Wl2[k * 320 + c] * is32);
    }
    if (i < 3 * 4096) {
        int p = i >> 12, r = i & 4095;
        const float* w0 = (p == 0) ? Wpre0 : (p == 1) ? Wn0 : Wo0;
        const float* w1 = (p == 0) ? Wpre1 : (p == 1) ? Wn1 : Wo1;
        g_eW[i] = pack2(w0[r] * 0.125f, w1[r] * 0.125f);
    }
    if (i < 2048) {
        int c = i >> 6, k = i & 63;
        g_Wf1T[c * 72 + k] = tf32f(Wf1[k * 32 + c] * 0.125f);
    }
    if (i < 4096) {
        int c = i >> 7, k = i & 127;
        float v = (k < 64) ? (Wl1[k * 32 + c] + Wl1[(64 + k) * 32 + c]) * r192
                           : Wl1[(64 + k) * 32 + c] * r192;
        g_Wl1T[c * 136 + k] = tf32f(v);
    }
}

// ---------------- e3_linear: 16 nodes/block --------------------------------
template<int IL, int OL, int OL2>
__global__ void e3_kernel(const float* __restrict__ in,
                          int widx,
                          const float* __restrict__ b0,
                          float* __restrict__ out,
                          float* __restrict__ out2, int nN) {
    extern __shared__ float sme3[];
    ull*   Wp  = (ull*)sme3;
    float* ins = sme3 + 8192;
    float* b0s = sme3 + 8192 + 4096;
    int tid = threadIdx.x;
    {
        const ull2* src = (const ull2*)(g_eW + widx * 4096);
        ull2* dst = (ull2*)Wp;
        for (int i = tid; i < 2048; i += 256) dst[i] = src[i];
    }
    if (tid < 64) b0s[tid] = b0[tid];
    int n0 = blockIdx.x * 16;
    if (IL == 0) {
        for (int i = tid; i < 256; i += 256) {
            int nl = i >> 4, g4 = i & 15;
            int u0 = g4 * 4;
            int n = n0 + nl;
            float4 a = make_float4(0.f,0.f,0.f,0.f), b = a, cc = a, dd = a;
            if (n < nN) {
                const float* xr = in + n * 256;
                a  = *(const float4*)(xr + u0);
                const float4* vp = (const float4*)(xr + 64 + u0 * 3);
                b = vp[0]; cc = vp[1]; dd = vp[2];
            }
            float4* q = (float4*)(ins + nl * 256 + u0 * 4);
            q[0] = make_float4(a.x, b.x, b.y, b.z);
            q[1] = make_float4(a.y, b.w, cc.x, cc.y);
            q[2] = make_float4(a.z, cc.z, cc.w, dd.x);
            q[3] = make_float4(a.w, dd.y, dd.z, dd.w);
        }
    } else {
        for (int i = tid; i < 1024; i += 256) {
            int nl = i >> 6, q = i & 63;
            int n = n0 + nl;
            float4 v = (n < nN) ? ((const float4*)(in + n * 256))[q]
                                : make_float4(0.f, 0.f, 0.f, 0.f);
            ((float4*)(ins + nl * 256))[q] = v;
        }
    }
    __syncthreads();
    int v = tid & 63, g = tid >> 6;
    const float* base = ins + g * 4 * 256;
    ull acc[4][2] = {};
    #pragma unroll 4
    for (int u = 0; u < 64; u++) {
        ull wp = Wp[u * 64 + v];
        float w0, w1; unpack2(wp, w0, w1);
        ull wq = pack2(w1, w1);
        #pragma unroll
        for (int t = 0; t < 4; t++) {
            ull2 q = *(const ull2*)(base + t * 256 + u * 4);
            fma2(acc[t][0], wp, q.x);
            fma2(acc[t][1], wq, q.y);
        }
    }
    float bias = b0s[v];
    float rs[4], r0[4], r1[4], r2[4];
    #pragma unroll
    for (int t = 0; t < 4; t++) {
        unpack2(acc[t][0], rs[t], r0[t]);
        unpack2(acc[t][1], r1[t], r2[t]);
        rs[t] += bias;
    }
    #pragma unroll
    for (int t = 0; t < 4; t++) {
        int n = n0 + g * 4 + t;
        if (n >= nN) continue;
        float4 q = make_float4(rs[t], r0[t], r1[t], r2[t]);
        if (OL == 1) ((float4*)(out + n * 256))[v] = q;
        if (out2 && OL2 == 1) ((float4*)(out2 + n * 256))[v] = q;
    }
    if (OL == 0) {
        __syncthreads();
        #pragma unroll
        for (int t = 0; t < 4; t++) {
            float* row = ins + (g * 4 + t) * 256;
            row[v] = rs[t];
            row[64 + v * 3 + 0] = r0[t];
            row[64 + v * 3 + 1] = r1[t];
            row[64 + v * 3 + 2] = r2[t];
        }
        __syncthreads();
        for (int i = tid; i < 1024; i += 256) {
            int nl = i >> 6, q = i & 63;
            int n = n0 + nl;
            if (n < nN)
                ((float4*)(out + n * 256))[q] = ((float4*)(ins + nl * 256))[q];
        }
    }
}

// ---------------- gate MLP (fp32 f32x2, 64 nodes/block, 512 thr) ------------
__global__ void __launch_bounds__(512, 1)
gate_kernel(const float* __restrict__ x,
            const float* __restrict__ Wg1,
            const float* __restrict__ bg1,
            const float* __restrict__ Wg2,
            const float* __restrict__ bg2,
            float* __restrict__ outb, int nN) {
    extern __shared__ float sm[];
    float* W1s = sm;
    float* W2s = sm + 16384;
    float* f0t = sm + 32768;
    float* hst = sm + 41472;
    int tid = threadIdx.x;
    for (int i = tid; i < 4096; i += 512) {
        ((float4*)W1s)[i] = ((const float4*)Wg1)[i];
        ((float4*)W2s)[i] = ((const float4*)Wg2)[i];
    }
    int n0 = blockIdx.x * 64;
    for (int i = tid; i < 8192; i += 512) {
        int nl = i & 63, j = i >> 6;
        int n = n0 + nl;
        float val = 0.f;
        if (n < nN) {
            const float* xr = x + n * 256;
            if (j < 64) val = xr[j];
            else {
                int u = j - 64;
                float v0 = xr[64 + u * 3], v1 = xr[64 + u * 3 + 1], v2 = xr[64 + u * 3 + 2];
                val = sqrtf(v0 * v0 + v1 * v1 + v2 * v2 + 1e-12f);
            }
        }
        f0t[j * 68 + nl] = val;
    }
    __syncthreads();
    int j = tid & 127, quarter = tid >> 7;
    int nb = quarter * 16;
    {
        ull a[8] = {};
        #pragma unroll 4
        for (int k = 0; k < 128; k++) {
            float w = W1s[k * 128 + j];
            ull wp = pack2(w, w);
            const ull2* f = (const ull2*)&f0t[k * 68 + nb];
            #pragma unroll
            for (int q = 0; q < 4; q++) {
                ull2 v = f[q];
                fma2(a[q * 2], wp, v.x);
                fma2(a[q * 2 + 1], wp, v.y);
            }
        }
        float b = bg1[j];
        #pragma unroll
        for (int q = 0; q < 8; q++) {
            float lo, hi; unpack2(a[q], lo, hi);
            hst[j * 68 + nb + q * 2]     = siluf(lo + b);
            hst[j * 68 + nb + q * 2 + 1] = siluf(hi + b);
        }
    }
    __syncthreads();
    float g[16];
    {
        ull a[8] = {};
        #pragma unroll 4
        for (int k = 0; k < 128; k++) {
            float w = W2s[k * 128 + j];
            ull wp = pack2(w, w);
            const ull2* h = (const ull2*)&hst[k * 68 + nb];
            #pragma unroll
            for (int q = 0; q < 4; q++) {
                ull2 v = h[q];
                fma2(a[q * 2], wp, v.x);
                fma2(a[q * 2 + 1], wp, v.y);
            }
        }
        float b = bg2[j];
        #pragma unroll
        for (int q = 0; q < 8; q++) {
            unpack2(a[q], g[q * 2], g[q * 2 + 1]);
            g[q * 2] += b; g[q * 2 + 1] += b;
        }
    }
    #pragma unroll
    for (int p = 0; p < 16; p++) f0t[(nb + p) * 128 + j] = g[p];
    __syncthreads();
    for (int q2 = tid; q2 < 4096; q2 += 512) {
        int nl = q2 >> 6, u = q2 & 63;
        int n = n0 + nl;
        if (n >= nN) continue;
        float gs = f0t[nl * 128 + u];
        float gv = f0t[nl * 128 + 64 + u];
        const float* xr = x + n * 256 + 64 + u * 3;
        ((float4*)(outb + n * 256))[u] = make_float4(gs, xr[0] * gv, xr[1] * gv, xr[2] * gv);
    }
}

// ---------------- h1a: tf32 MMA (outputs tf32-rounded) ----------------------
__global__ void __launch_bounds__(256, 2)
h1a_mma(const float* __restrict__ attr, float* __restrict__ h1a, int nE) {
    extern __shared__ float sa[];
    float* at = sa;
    float* BT = sa + 8704;
    int tid = threadIdx.x;
    int e0 = blockIdx.x * 128;
    for (int i = tid; i < 576; i += 256)
        ((float4*)BT)[i] = ((const float4*)g_Wf1T)[i];
    for (int i = tid; i < 2048; i += 256) {
        int el = i >> 4, u0 = (i & 15) * 4;
        int e = e0 + el;
        float4 a4 = (e < nE) ? *(const float4*)&attr[e * 64 + u0]
                             : make_float4(0.f, 0.f, 0.f, 0.f);
        *(float4*)&at[el * 68 + u0] =
            make_float4(tf32f(a4.x), tf32f(a4.y), tf32f(a4.z), tf32f(a4.w));
    }
    __syncthreads();
    int lane = tid & 31, w = tid >> 5;
    int group = lane >> 2, tig = lane & 3;
    int m0 = w * 16;
    int rowA = (m0 + group) * 68;
    float acc[4][4] = {};
    #pragma unroll 1
    for (int ks = 0; ks < 8; ks++) {
        int c = ks * 8 + tig;
        unsigned a[4];
        a[0] = __float_as_uint(at[rowA + c]);
        a[1] = __float_as_uint(at[rowA + 544 + c]);
        a[2] = __float_as_uint(at[rowA + c + 4]);
        a[3] = __float_as_uint(at[rowA + 544 + c + 4]);
        #pragma unroll
        for (int j = 0; j < 4; j++) {
            unsigned b[2];
            int br = (j * 8 + group) * 72 + ks * 8 + tig;
            b[0] = __float_as_uint(BT[br]);
            b[1] = __float_as_uint(BT[br + 4]);
            mma_tf32(acc[j], a, b);
        }
    }
    int eA = e0 + m0 + group, eB = eA + 8;
    #pragma unroll
    for (int j = 0; j < 4; j++) {
        int c0 = j * 8 + 2 * tig;
        if (eA < nE)
            *(float2*)&h1a[eA * 32 + c0] =
                make_float2(tf32f(sspf(acc[j][0])), tf32f(sspf(acc[j][1])));
        if (eB < nE)
            *(float2*)&h1a[eB * 32 + c0] =
                make_float2(tf32f(sspf(acc[j][2])), tf32f(sspf(acc[j][3])));
    }
}

// ---------------- h1l: tf32 MMA (outputs tf32-rounded) ----------------------
__global__ void __launch_bounds__(256, 2)
h1l_mma(const int* __restrict__ ei, const float* __restrict__ pre,
        float* __restrict__ h1l, int nE, int Etot) {
    extern __shared__ float sl[];
    float* st = sl;
    float* BT = sl + 16896;
    int*   idx = (int*)(sl + 21248);
    int tid = threadIdx.x;
    int e0 = blockIdx.x * 128;
    for (int i = tid; i < 1088; i += 256)
        ((float4*)BT)[i] = ((const float4*)g_Wl1T)[i];
    if (tid < 128) {
        int e = e0 + tid;
        bool v = (e < nE);
        idx[tid]       = v ? ei[e] : 0;
        idx[128 + tid] = v ? ei[Etot + e] : 0;
    }
    __syncthreads();
    for (int i = tid; i < 8192; i += 256) {
        int el = i >> 6, u = i & 63;
        int d = idx[el], s = idx[128 + el];
        float4 qd = *(const float4*)&pre[d * 256 + u * 4];
        float4 qs = *(const float4*)&pre[s * 256 + u * 4];
        st[el * 132 + u] = tf32f(qd.x);
        st[el * 132 + 64 + u] =
            tf32f((qd.y * qs.y + qd.z * qs.z + qd.w * qs.w) * (1.f / 3.f));
    }
    __syncthreads();
    int lane = tid & 31, w = tid >> 5;
    int group = lane >> 2, tig = lane & 3;
    int m0 = w * 16;
    int rowA = (m0 + group) * 132;
    float acc[4][4] = {};
    #pragma unroll 1
    for (int ks = 0; ks < 16; ks++) {
        int c = ks * 8 + tig;
        unsigned a[4];
        a[0] = __float_as_uint(st[rowA + c]);
        a[1] = __float_as_uint(st[rowA + 1056 + c]);
        a[2] = __float_as_uint(st[rowA + c + 4]);
        a[3] = __float_as_uint(st[rowA + 1056 + c + 4]);
        #pragma unroll
        for (int j = 0; j < 4; j++) {
            unsigned b[2];
            int br = (j * 8 + group) * 136 + ks * 8 + tig;
            b[0] = __float_as_uint(BT[br]);
            b[1] = __float_as_uint(BT[br + 4]);
            mma_tf32(acc[j], a, b);
        }
    }
    int eA = e0 + m0 + group, eB = eA + 8;
    #pragma unroll
    for (int j = 0; j < 4; j++) {
        int c0 = j * 8 + 2 * tig;
        if (eA < nE)
            *(float2*)&h1l[eA * 32 + c0] =
                make_float2(tf32f(sspf(acc[j][0])), tf32f(sspf(acc[j][1])));
        if (eB < nE)
            *(float2*)&h1l[eB * 32 + c0] =
                make_float2(tf32f(sspf(acc[j][2])), tf32f(sspf(acc[j][3])));
    }
}

// ---------------- fused edge kernel: PERSISTENT + cp.async + MLP8 phase2 ----
#define TE 64
#define HRS 36
#define WSS 324
#define EDGE_BLOCKS 296
__global__ void __launch_bounds__(320, 2)
edge_kernel(const int* __restrict__ ei,
            const float* __restrict__ sh,
            const float* __restrict__ h1a,
            const float* __restrict__ h1l,
            const float* __restrict__ xg,
            float* __restrict__ acc, int nE, int Etot) {
    extern __shared__ float sm[];
    float* hA  = sm;
    float* hB  = sm + 2304;
    float* ws  = sm + 4608;
    float* WlS = sm + 14976;
    float* shs = sm + 26496;
    int*   idxs = (int*)(sm + 26752);
    int tid = threadIdx.x;
    int lane = tid & 31, wrp = tid >> 5;
    int group = lane >> 2, tig = lane & 3;

    unsigned bf[4][4][2];
    #pragma unroll
    for (int j = 0; j < 4; j++) {
        int n0 = (wrp * 4 + j) * 8;
        #pragma unroll
        for (int ks = 0; ks < 4; ks++) {
            bf[j][ks][0] = __float_as_uint(g_WfT[(n0 + group) * 32 + ks * 8 + tig]);
            bf[j][ks][1] = __float_as_uint(g_WfT[(n0 + group) * 32 + ks * 8 + tig + 4]);
        }
    }
    for (int i = tid; i < 10240; i += 320) {
        int col = i >> 5, k = i & 31;
        WlS[col * 36 + k] = g_WlT[col * 32 + k];
    }

    unsigned hA_s = (unsigned)__cvta_generic_to_shared(hA);
    unsigned hB_s = (unsigned)__cvta_generic_to_shared(hB);

    const float PW_S = 0.44721359549995793f;
    const float PW_V = 0.77459666924148337f;
    const float IS3  = 0.57735026918962576f;
    const float IS2  = 0.70710678118654752f;

    int t = tid - 256;
    int psrc = 0, pdst = -1;
    float4 psh = make_float4(0.f, 0.f, 0.f, 0.f);

    {
        int e0 = blockIdx.x * TE;
        if (t >= 0) {
            int e = e0 + t;
            bool v = (e < nE);
            pdst = v ? ei[e] : -1;
            psrc = v ? ei[Etot + e] : 0;
            psh  = v ? *(const float4*)&sh[e * 4] : make_float4(0.f, 0.f, 0.f, 0.f);
            const float* sa = h1a + (v ? e : 0) * 32;
            const float* sb = h1l + (v ? e : 0) * 32;
            int sz = v ? 16 : 0;
            #pragma unroll
            for (int c = 0; c < 8; c++) {
                cpa16(hA_s + t * 144 + c * 16, sa + c * 4, sz);
                cpa16(hB_s + t * 144 + c * 16, sb + c * 4, sz);
            }
        }
        asm volatile("cp.async.commit_group;" ::: "memory");
    }

    int ntiles = (nE + TE - 1) / TE;
    for (int tile = blockIdx.x; tile < ntiles; tile += gridDim.x) {
        if (t >= 0) {
            idxs[t]      = psrc;
            idxs[64 + t] = pdst;
            ((float4*)shs)[t] = psh;
        }
        asm volatile("cp.async.wait_group 0;" ::: "memory");
        __syncthreads();
        int next = tile + gridDim.x;

        #pragma unroll 1
        for (int half = 0; half < 2; half++) {
            #pragma unroll 1
            for (int mm = 0; mm < 2; mm++) {
                int m0 = (half * 2 + mm) * 16;
                int rowA = (m0 + group) * HRS;
                float dA[4][4] = {}, dB[4][4] = {};
                #pragma unroll
                for (int ks = 0; ks < 4; ks++) {
                    int c = ks * 8 + tig;
                    unsigned aA[4], aB[4];
                    aA[0] = __float_as_uint(hA[rowA + c]);
                    aA[1] = __float_as_uint(hA[rowA + 8 * HRS + c]);
                    aA[2] = __float_as_uint(hA[rowA + c + 4]);
                    aA[3] = __float_as_uint(hA[rowA + 8 * HRS + c + 4]);
                    aB[0] = __float_as_uint(hB[rowA + c]);
                    aB[1] = __float_as_uint(hB[rowA + 8 * HRS + c]);
                    aB[2] = __float_as_uint(hB[rowA + c + 4]);
                    aB[3] = __float_as_uint(hB[rowA + 8 * HRS + c + 4]);
                    #pragma unroll
                    for (int j = 0; j < 4; j++) {
                        mma_tf32(dA[j], aA, bf[j][ks]);
                        unsigned bl[2];
                        int br = ((wrp * 4 + j) * 8 + group) * 36 + ks * 8 + tig;
                        bl[0] = __float_as_uint(WlS[br]);
                        bl[1] = __float_as_uint(WlS[br + 4]);
                        mma_tf32(dB[j], aB, bl);
                    }
                }
                int lrow = mm * 16 + group;
                #pragma unroll
                for (int j = 0; j < 4; j++) {
                    int col0 = (wrp * 4 + j) * 8 + 2 * tig;
                    *(float2*)&ws[lrow * WSS + col0] =
                        make_float2(dA[j][0] * dB[j][0], dA[j][1] * dB[j][1]);
                    *(float2*)&ws[(lrow + 8) * WSS + col0] =
                        make_float2(dA[j][2] * dB[j][2], dA[j][3] * dB[j][3]);
                }
            }
            __syncthreads();
            if (half == 1) {
                if (t >= 0 && next < ntiles) {
                    int e = next * TE + t;
                    bool v = (e < nE);
                    pdst = v ? ei[e] : -1;
                    psrc = v ? ei[Etot + e] : 0;
                    psh  = v ? *(const float4*)&sh[e * 4] : make_float4(0.f, 0.f, 0.f, 0.f);
                    const float* sa = h1a + (v ? e : 0) * 32;
                    const float* sb = h1l + (v ? e : 0) * 32;
                    int sz = v ? 16 : 0;
                    #pragma unroll
                    for (int c = 0; c < 8; c++) {
                        cpa16(hA_s + t * 144 + c * 16, sa + c * 4, sz);
                        cpa16(hB_s + t * 144 + c * 16, sb + c * 4, sz);
                    }
                }
                asm volatile("cp.async.commit_group;" ::: "memory");
            }
            // ---- phase 2: MLP-8 gather batch, then compute ----
            if (tid < 256) {
                int u = tid & 63, grp = tid >> 6;
                int ebase = half * 32 + grp * 8;
                int ds[8], ss[8];
                #pragma unroll
                for (int e2 = 0; e2 < 8; e2++) {
                    ds[e2] = idxs[64 + ebase + e2];
                    ss[e2] = idxs[ebase + e2];
                }
                float4 q[8];
                #pragma unroll
                for (int e2 = 0; e2 < 8; e2++) {
                    int s = (ds[e2] >= 0) ? ss[e2] : 0;
                    q[e2] = *(const float4*)&xg[s * 256 + u * 4];
                }
                #pragma unroll
                for (int e2 = 0; e2 < 8; e2++) {
                    int d = ds[e2];
                    if (d < 0) continue;
                    int el = ebase + e2;
                    float es = q[e2].x, ev0 = q[e2].y, ev1 = q[e2].z, ev2 = q[e2].w;
                    float4 shq = ((const float4*)shs)[el];
                    float s0 = shq.x, s1 = shq.y, s2 = shq.z, s3 = shq.w;
                    const float* we = ws + (el - half * 32) * WSS;
                    float w0 = we[u], w1 = we[64 + u], w2 = we[128 + u];
                    float w3 = we[192 + u], w4 = we[256 + u];
                    float dotv = ev0 * s1 + ev1 * s2 + ev2 * s3;
                    float c0 = ev1 * s3 - ev2 * s2;
                    float c1 = ev2 * s1 - ev0 * s3;
                    float c2 = ev0 * s2 - ev1 * s1;
                    float outs = PW_S * (w0 * es * s0 + w3 * dotv * IS3);
                    float k2 = PW_V * w2 * s0;
                    float k4 = PW_V * w4 * IS2;
                    float k1 = PW_V * w1 * es;
                    float o0 = k1 * s1 + k2 * ev0 + k4 * c0;
                    float o1 = k1 * s2 + k2 * ev1 + k4 * c1;
                    float o2 = k1 * s3 + k2 * ev2 + k4 * c2;
                    float* pa = acc + d * 256 + u * 4;
                    asm volatile("red.global.add.v4.f32 [%0], {%1, %2, %3, %4};"
                                 :: "l"(pa), "f"(outs), "f"(o0), "f"(o1), "f"(o2) : "memory");
                }
            }
            __syncthreads();
        }
    }
}

// ---------------- launch ----------------------------------------------------
extern "C" void kernel_launch(void* const* d_in, const int* in_sizes, int n_in,
                              void* d_out, int out_size) {
    const float* x     = (const float*)d_in[0];
    const int*   ei    = (const int*)  d_in[1];
    const float* sh    = (const float*)d_in[2];
    const float* attr  = (const float*)d_in[3];
    const float* Wpre0 = (const float*)d_in[4];
    const float* bpre0 = (const float*)d_in[5];
    const float* Wpre1 = (const float*)d_in[6];
    const float* Wg1   = (const float*)d_in[7];
    const float* bg1   = (const float*)d_in[8];
    const float* Wg2   = (const float*)d_in[9];
    const float* bg2   = (const float*)d_in[10];
    const float* Wn0   = (const float*)d_in[11];
    const float* bn0   = (const float*)d_in[12];
    const float* Wn1   = (const float*)d_in[13];
    const float* Wf1   = (const float*)d_in[14];
    const float* Wf2   = (const float*)d_in[15];
    const float* Wl1   = (const float*)d_in[16];
    const float* Wl2   = (const float*)d_in[17];
    const float* Wo0   = (const float*)d_in[18];
    const float* bo0   = (const float*)d_in[19];
    const float* Wo1   = (const float*)d_in[20];

    int N = in_sizes[0] / 256;
    int E = in_sizes[1] / 2;

    float *pre, *tmp, *xgp, *accp, *h1a, *h1l;
    cudaGetSymbolAddress((void**)&pre,  g_pre);
    cudaGetSymbolAddress((void**)&tmp,  g_tmp);
    cudaGetSymbolAddress((void**)&xgp,  g_xg);
    cudaGetSymbolAddress((void**)&accp, g_acc);
    cudaGetSymbolAddress((void**)&h1a,  g_h1a);
    cudaGetSymbolAddress((void**)&h1l,  g_h1l);

    static const int E3_SMEM   = (8192 + 4096 + 64) * 4;
    static const int GATE_SMEM = (16384 * 2 + 8704 * 2) * 4;
    static const int H1A_SMEM  = (8704 + 2304) * 4;
    static const int H1L_SMEM  = (16896 + 4352 + 256) * 4;
    static const int EDGE_SMEM = (2304 * 2 + 10368 + 11520 + 256 + 128) * 4;
    cudaFuncSetAttribute(e3_kernel<0,1,1>, cudaFuncAttributeMaxDynamicSharedMemorySize, E3_SMEM);
    cudaFuncSetAttribute(e3_kernel<1,1,1>, cudaFuncAttributeMaxDynamicSharedMemorySize, E3_SMEM);
    cudaFuncSetAttribute(e3_kernel<1,0,0>, cudaFuncAttributeMaxDynamicSharedMemorySize, E3_SMEM);
    cudaFuncSetAttribute(gate_kernel, cudaFuncAttributeMaxDynamicSharedMemorySize, GATE_SMEM);
    cudaFuncSetAttribute(h1a_mma,  cudaFuncAttributeMaxDynamicSharedMemorySize, H1A_SMEM);
    cudaFuncSetAttribute(h1l_mma,  cudaFuncAttributeMaxDynamicSharedMemorySize, H1L_SMEM);
    cudaFuncSetAttribute(edge_kernel, cudaFuncAttributeMaxDynamicSharedMemorySize, EDGE_SMEM);

    static cudaStream_t s1 = nullptr, s2 = nullptr;
    static cudaEvent_t ev0, evP, ev1, ev2;
    if (!s1) {
        cudaStreamCreateWithFlags(&s1, cudaStreamNonBlocking);
        cudaStreamCreateWithFlags(&s2, cudaStreamNonBlocking);
        cudaEventCreateWithFlags(&ev0, cudaEventDisableTiming);
        cudaEventCreateWithFlags(&evP, cudaEventDisableTiming);
        cudaEventCreateWithFlags(&ev1, cudaEventDisableTiming);
        cudaEventCreateWithFlags(&ev2, cudaEventDisableTiming);
    }
    cudaStream_t d = 0;

    cudaEventRecord(ev0, d);
    cudaStreamWaitEvent(s1, ev0, 0);
    gate_kernel<<<(N + 63) / 64, 512, GATE_SMEM, s1>>>(x, Wg1, bg1, Wg2, bg2, tmp, N);

    prep_kernel<<<48, 256, 0, d>>>(Wf2, Wl2, Wl1, Wpre0, Wpre1, Wn0, Wn1, Wo0, Wo1, Wf1);
    cudaEventRecord(evP, d);
    cudaStreamWaitEvent(s2, evP, 0);

    h1a_mma<<<(E + 127) / 128, 256, H1A_SMEM, s2>>>(attr, h1a, E);
    cudaEventRecord(ev2, s2);

    e3_kernel<0, 1, 1><<<(N + 15) / 16, 256, E3_SMEM, d>>>(x, 0, bpre0, pre, nullptr, N);
    h1l_mma<<<(E + 127) / 128, 256, H1L_SMEM, d>>>(ei, pre, h1l, E, E);

    cudaStreamWaitEvent(s1, evP, 0);
    e3_kernel<1, 1, 1><<<(N + 15) / 16, 256, E3_SMEM, s1>>>(tmp, 1, bn0, xgp, accp, N);
    cudaEventRecord(ev1, s1);

    cudaStreamWaitEvent(d, ev1, 0);
    cudaStreamWaitEvent(d, ev2, 0);
    int ntiles = (E + TE - 1) / TE;
    int eblocks = ntiles < EDGE_BLOCKS ? ntiles : EDGE_BLOCKS;
    edge_kernel<<<eblocks, 320, EDGE_SMEM, d>>>(ei, sh, h1a, h1l, xgp, accp, E, E);
    e3_kernel<1, 0, 0><<<(N + 15) / 16, 256, E3_SMEM, d>>>(accp, 2, bo0, (float*)d_out, nullptr, N);
}

// round 16
// speedup vs baseline: 1.1039x; 1.0044x over previous
#include <cuda_runtime.h>
#include <math.h>

#define MAXN 20000
#define MAXE 320000

typedef unsigned long long ull;
typedef ulonglong2 ull2;

// ---------------- scratch (device globals) ---------------------------------
__device__ float g_pre[MAXN * 256];
__device__ float g_tmp[MAXN * 256];
__device__ float g_xg [MAXN * 256];
__device__ float g_acc[MAXN * 256];
__device__ float g_h1a[MAXE * 32];
__device__ float g_h1l[MAXE * 32];
__device__ float g_WfT[320 * 32];
__device__ float g_WlT[320 * 32];
__device__ float g_Wf1T[32 * 72];
__device__ float g_Wl1T[32 * 136];
__device__ ull   g_eW[3 * 4096];
__device__ int   g_tilectr;

__device__ __forceinline__ float sspf(float x) {
    float sp = (x > 15.f) ? x : log1pf(expf(x));
    return sp - 0.69314718055994531f;
}
__device__ __forceinline__ float siluf(float x) {
    return x / (1.f + expf(-x));
}
__device__ __forceinline__ ull pack2(float a, float b) {
    ull r; asm("mov.b64 %0, {%1, %2};" : "=l"(r) : "f"(a), "f"(b)); return r;
}
__device__ __forceinline__ void fma2(ull& d, ull a, ull b) {
    asm("fma.rn.f32x2 %0, %1, %2, %0;" : "+l"(d) : "l"(a), "l"(b));
}
__device__ __forceinline__ void unpack2(ull v, float& lo, float& hi) {
    asm("mov.b64 {%0, %1}, %2;" : "=f"(lo), "=f"(hi) : "l"(v));
}
__device__ __forceinline__ unsigned tf32r(float x) {
    unsigned r; asm("cvt.rna.tf32.f32 %0, %1;" : "=r"(r) : "f"(x)); return r;
}
__device__ __forceinline__ float tf32f(float x) {
    return __uint_as_float(tf32r(x));
}
__device__ __forceinline__ void mma_tf32(float* d, const unsigned* a, const unsigned* b) {
    asm("mma.sync.aligned.m16n8k8.row.col.f32.tf32.tf32.f32 "
        "{%0,%1,%2,%3}, {%4,%5,%6,%7}, {%8,%9}, {%0,%1,%2,%3};"
        : "+f"(d[0]), "+f"(d[1]), "+f"(d[2]), "+f"(d[3])
        : "r"(a[0]), "r"(a[1]), "r"(a[2]), "r"(a[3]), "r"(b[0]), "r"(b[1]));
}
__device__ __forceinline__ void cpa16(unsigned dst, const float* src, int sz) {
    asm volatile("cp.async.cg.shared.global [%0], [%1], 16, %2;"
                 :: "r"(dst), "l"(src), "r"(sz) : "memory");
}

// ---------------- weight prep ----------------------------------------------
#define EDGE_BLOCKS 296
__global__ void prep_kernel(const float* __restrict__ Wf2,
                            const float* __restrict__ Wl2,
                            const float* __restrict__ Wl1,
                            const float* __restrict__ Wpre0,
                            const float* __restrict__ Wpre1,
                            const float* __restrict__ Wn0,
                            const float* __restrict__ Wn1,
                            const float* __restrict__ Wo0,
                            const float* __restrict__ Wo1,
                            const float* __restrict__ Wf1) {
    int i = blockIdx.x * 256 + threadIdx.x;
    if (i == 0) g_tilectr = EDGE_BLOCKS;
    const float is32 = 0.17677669529663687f;
    const float r192 = 0.07216878364870323f;
    if (i < 320 * 32) {
        int c = i >> 5, k = i & 31;
        g_WfT[i] = tf32f(Wf2[k * 320 + c] * is32);
        g_WlT[i] = tf32f(Wl2[k * 320 + c] * is32);
    }
    if (i < 3 * 4096) {
        int p = i >> 12, r = i & 4095;
        const float* w0 = (p == 0) ? Wpre0 : (p == 1) ? Wn0 : Wo0;
        const float* w1 = (p == 0) ? Wpre1 : (p == 1) ? Wn1 : Wo1;
        g_eW[i] = pack2(w0[r] * 0.125f, w1[r] * 0.125f);
    }
    if (i < 2048) {
        int c = i >> 6, k = i & 63;
        g_Wf1T[c * 72 + k] = tf32f(Wf1[k * 32 + c] * 0.125f);
    }
    if (i < 4096) {
        int c = i >> 7, k = i & 127;
        float v = (k < 64) ? (Wl1[k * 32 + c] + Wl1[(64 + k) * 32 + c]) * r192
                           : Wl1[(64 + k) * 32 + c] * r192;
        g_Wl1T[c * 136 + k] = tf32f(v);
    }
}

// ---------------- e3_linear: 16 nodes/block --------------------------------
template<int IL, int OL, int OL2>
__global__ void e3_kernel(const float* __restrict__ in,
                          int widx,
                          const float* __restrict__ b0,
                          float* __restrict__ out,
                          float* __restrict__ out2, int nN) {
    extern __shared__ float sme3[];
    ull*   Wp  = (ull*)sme3;
    float* ins = sme3 + 8192;
    float* b0s = sme3 + 8192 + 4096;
    int tid = threadIdx.x;
    {
        const ull2* src = (const ull2*)(g_eW + widx * 4096);
        ull2* dst = (ull2*)Wp;
        for (int i = tid; i < 2048; i += 256) dst[i] = src[i];
    }
    if (tid < 64) b0s[tid] = b0[tid];
    int n0 = blockIdx.x * 16;
    if (IL == 0) {
        for (int i = tid; i < 256; i += 256) {
            int nl = i >> 4, g4 = i & 15;
            int u0 = g4 * 4;
            int n = n0 + nl;
            float4 a = make_float4(0.f,0.f,0.f,0.f), b = a, cc = a, dd = a;
            if (n < nN) {
                const float* xr = in + n * 256;
                a  = *(const float4*)(xr + u0);
                const float4* vp = (const float4*)(xr + 64 + u0 * 3);
                b = vp[0]; cc = vp[1]; dd = vp[2];
            }
            float4* q = (float4*)(ins + nl * 256 + u0 * 4);
            q[0] = make_float4(a.x, b.x, b.y, b.z);
            q[1] = make_float4(a.y, b.w, cc.x, cc.y);
            q[2] = make_float4(a.z, cc.z, cc.w, dd.x);
            q[3] = make_float4(a.w, dd.y, dd.z, dd.w);
        }
    } else {
        for (int i = tid; i < 1024; i += 256) {
            int nl = i >> 6, q = i & 63;
            int n = n0 + nl;
            float4 v = (n < nN) ? ((const float4*)(in + n * 256))[q]
                                : make_float4(0.f, 0.f, 0.f, 0.f);
            ((float4*)(ins + nl * 256))[q] = v;
        }
    }
    __syncthreads();
    int v = tid & 63, g = tid >> 6;
    const float* base = ins + g * 4 * 256;
    ull acc[4][2] = {};
    #pragma unroll 4
    for (int u = 0; u < 64; u++) {
        ull wp = Wp[u * 64 + v];
        float w0, w1; unpack2(wp, w0, w1);
        ull wq = pack2(w1, w1);
        #pragma unroll
        for (int t = 0; t < 4; t++) {
            ull2 q = *(const ull2*)(base + t * 256 + u * 4);
            fma2(acc[t][0], wp, q.x);
            fma2(acc[t][1], wq, q.y);
        }
    }
    float bias = b0s[v];
    float rs[4], r0[4], r1[4], r2[4];
    #pragma unroll
    for (int t = 0; t < 4; t++) {
        unpack2(acc[t][0], rs[t], r0[t]);
        unpack2(acc[t][1], r1[t], r2[t]);
        rs[t] += bias;
    }
    #pragma unroll
    for (int t = 0; t < 4; t++) {
        int n = n0 + g * 4 + t;
        if (n >= nN) continue;
        float4 q = make_float4(rs[t], r0[t], r1[t], r2[t]);
        if (OL == 1) ((float4*)(out + n * 256))[v] = q;
        if (out2 && OL2 == 1) ((float4*)(out2 + n * 256))[v] = q;
    }
    if (OL == 0) {
        __syncthreads();
        #pragma unroll
        for (int t = 0; t < 4; t++) {
            float* row = ins + (g * 4 + t) * 256;
            row[v] = rs[t];
            row[64 + v * 3 + 0] = r0[t];
            row[64 + v * 3 + 1] = r1[t];
            row[64 + v * 3 + 2] = r2[t];
        }
        __syncthreads();
        for (int i = tid; i < 1024; i += 256) {
            int nl = i >> 6, q = i & 63;
            int n = n0 + nl;
            if (n < nN)
                ((float4*)(out + n * 256))[q] = ((float4*)(ins + nl * 256))[q];
        }
    }
}

// ---------------- gate MLP (fp32 f32x2, 64 nodes/block, 512 thr) ------------
__global__ void __launch_bounds__(512, 1)
gate_kernel(const float* __restrict__ x,
            const float* __restrict__ Wg1,
            const float* __restrict__ bg1,
            const float* __restrict__ Wg2,
            const float* __restrict__ bg2,
            float* __restrict__ outb, int nN) {
    extern __shared__ float sm[];
    float* W1s = sm;
    float* W2s = sm + 16384;
    float* f0t = sm + 32768;
    float* hst = sm + 41472;
    int tid = threadIdx.x;
    for (int i = tid; i < 4096; i += 512) {
        ((float4*)W1s)[i] = ((const float4*)Wg1)[i];
        ((float4*)W2s)[i] = ((const float4*)Wg2)[i];
    }
    int n0 = blockIdx.x * 64;
    for (int i = tid; i < 8192; i += 512) {
        int nl = i & 63, j = i >> 6;
        int n = n0 + nl;
        float val = 0.f;
        if (n < nN) {
            const float* xr = x + n * 256;
            if (j < 64) val = xr[j];
            else {
                int u = j - 64;
                float v0 = xr[64 + u * 3], v1 = xr[64 + u * 3 + 1], v2 = xr[64 + u * 3 + 2];
                val = sqrtf(v0 * v0 + v1 * v1 + v2 * v2 + 1e-12f);
            }
        }
        f0t[j * 68 + nl] = val;
    }
    __syncthreads();
    int j = tid & 127, quarter = tid >> 7;
    int nb = quarter * 16;
    {
        ull a[8] = {};
        #pragma unroll 4
        for (int k = 0; k < 128; k++) {
            float w = W1s[k * 128 + j];
            ull wp = pack2(w, w);
            const ull2* f = (const ull2*)&f0t[k * 68 + nb];
            #pragma unroll
            for (int q = 0; q < 4; q++) {
                ull2 v = f[q];
                fma2(a[q * 2], wp, v.x);
                fma2(a[q * 2 + 1], wp, v.y);
            }
        }
        float b = bg1[j];
        #pragma unroll
        for (int q = 0; q < 8; q++) {
            float lo, hi; unpack2(a[q], lo, hi);
            hst[j * 68 + nb + q * 2]     = siluf(lo + b);
            hst[j * 68 + nb + q * 2 + 1] = siluf(hi + b);
        }
    }
    __syncthreads();
    float g[16];
    {
        ull a[8] = {};
        #pragma unroll 4
        for (int k = 0; k < 128; k++) {
            float w = W2s[k * 128 + j];
            ull wp = pack2(w, w);
            const ull2* h = (const ull2*)&hst[k * 68 + nb];
            #pragma unroll
            for (int q = 0; q < 4; q++) {
                ull2 v = h[q];
                fma2(a[q * 2], wp, v.x);
                fma2(a[q * 2 + 1], wp, v.y);
            }
        }
        float b = bg2[j];
        #pragma unroll
        for (int q = 0; q < 8; q++) {
            unpack2(a[q], g[q * 2], g[q * 2 + 1]);
            g[q * 2] += b; g[q * 2 + 1] += b;
        }
    }
    #pragma unroll
    for (int p = 0; p < 16; p++) f0t[(nb + p) * 128 + j] = g[p];
    __syncthreads();
    for (int q2 = tid; q2 < 4096; q2 += 512) {
        int nl = q2 >> 6, u = q2 & 63;
        int n = n0 + nl;
        if (n >= nN) continue;
        float gs = f0t[nl * 128 + u];
        float gv = f0t[nl * 128 + 64 + u];
        const float* xr = x + n * 256 + 64 + u * 3;
        ((float4*)(outb + n * 256))[u] = make_float4(gs, xr[0] * gv, xr[1] * gv, xr[2] * gv);
    }
}

// ---------------- h1a: tf32 MMA (outputs tf32-rounded) ----------------------
__global__ void __launch_bounds__(256, 2)
h1a_mma(const float* __restrict__ attr, float* __restrict__ h1a, int nE) {
    extern __shared__ float sa[];
    float* at = sa;
    float* BT = sa + 8704;
    int tid = threadIdx.x;
    int e0 = blockIdx.x * 128;
    for (int i = tid; i < 576; i += 256)
        ((float4*)BT)[i] = ((const float4*)g_Wf1T)[i];
    for (int i = tid; i < 2048; i += 256) {
        int el = i >> 4, u0 = (i & 15) * 4;
        int e = e0 + el;
        float4 a4 = (e < nE) ? *(const float4*)&attr[e * 64 + u0]
                             : make_float4(0.f, 0.f, 0.f, 0.f);
        *(float4*)&at[el * 68 + u0] =
            make_float4(tf32f(a4.x), tf32f(a4.y), tf32f(a4.z), tf32f(a4.w));
    }
    __syncthreads();
    int lane = tid & 31, w = tid >> 5;
    int group = lane >> 2, tig = lane & 3;
    int m0 = w * 16;
    int rowA = (m0 + group) * 68;
    float acc[4][4] = {};
    #pragma unroll 1
    for (int ks = 0; ks < 8; ks++) {
        int c = ks * 8 + tig;
        unsigned a[4];
        a[0] = __float_as_uint(at[rowA + c]);
        a[1] = __float_as_uint(at[rowA + 544 + c]);
        a[2] = __float_as_uint(at[rowA + c + 4]);
        a[3] = __float_as_uint(at[rowA + 544 + c + 4]);
        #pragma unroll
        for (int j = 0; j < 4; j++) {
            unsigned b[2];
            int br = (j * 8 + group) * 72 + ks * 8 + tig;
            b[0] = __float_as_uint(BT[br]);
            b[1] = __float_as_uint(BT[br + 4]);
            mma_tf32(acc[j], a, b);
        }
    }
    int eA = e0 + m0 + group, eB = eA + 8;
    #pragma unroll
    for (int j = 0; j < 4; j++) {
        int c0 = j * 8 + 2 * tig;
        if (eA < nE)
            *(float2*)&h1a[eA * 32 + c0] =
                make_float2(tf32f(sspf(acc[j][0])), tf32f(sspf(acc[j][1])));
        if (eB < nE)
            *(float2*)&h1a[eB * 32 + c0] =
                make_float2(tf32f(sspf(acc[j][2])), tf32f(sspf(acc[j][3])));
    }
}

// ---------------- h1l: tf32 MMA (outputs tf32-rounded) ----------------------
__global__ void __launch_bounds__(256, 2)
h1l_mma(const int* __restrict__ ei, const float* __restrict__ pre,
        float* __restrict__ h1l, int nE, int Etot) {
    extern __shared__ float sl[];
    float* st = sl;
    float* BT = sl + 16896;
    int*   idx = (int*)(sl + 21248);
    int tid = threadIdx.x;
    int e0 = blockIdx.x * 128;
    for (int i = tid; i < 1088; i += 256)
        ((float4*)BT)[i] = ((const float4*)g_Wl1T)[i];
    if (tid < 128) {
        int e = e0 + tid;
        bool v = (e < nE);
        idx[tid]       = v ? ei[e] : 0;
        idx[128 + tid] = v ? ei[Etot + e] : 0;
    }
    __syncthreads();
    for (int i = tid; i < 8192; i += 256) {
        int el = i >> 6, u = i & 63;
        int d = idx[el], s = idx[128 + el];
        float4 qd = *(const float4*)&pre[d * 256 + u * 4];
        float4 qs = *(const float4*)&pre[s * 256 + u * 4];
        st[el * 132 + u] = tf32f(qd.x);
        st[el * 132 + 64 + u] =
            tf32f((qd.y * qs.y + qd.z * qs.z + qd.w * qs.w) * (1.f / 3.f));
    }
    __syncthreads();
    int lane = tid & 31, w = tid >> 5;
    int group = lane >> 2, tig = lane & 3;
    int m0 = w * 16;
    int rowA = (m0 + group) * 132;
    float acc[4][4] = {};
    #pragma unroll 1
    for (int ks = 0; ks < 16; ks++) {
        int c = ks * 8 + tig;
        unsigned a[4];
        a[0] = __float_as_uint(st[rowA + c]);
        a[1] = __float_as_uint(st[rowA + 1056 + c]);
        a[2] = __float_as_uint(st[rowA + c + 4]);
        a[3] = __float_as_uint(st[rowA + 1056 + c + 4]);
        #pragma unroll
        for (int j = 0; j < 4; j++) {
            unsigned b[2];
            int br = (j * 8 + group) * 136 + ks * 8 + tig;
            b[0] = __float_as_uint(BT[br]);
            b[1] = __float_as_uint(BT[br + 4]);
            mma_tf32(acc[j], a, b);
        }
    }
    int eA = e0 + m0 + group, eB = eA + 8;
    #pragma unroll
    for (int j = 0; j < 4; j++) {
        int c0 = j * 8 + 2 * tig;
        if (eA < nE)
            *(float2*)&h1l[eA * 32 + c0] =
                make_float2(tf32f(sspf(acc[j][0])), tf32f(sspf(acc[j][1])));
        if (eB < nE)
            *(float2*)&h1l[eB * 32 + c0] =
                make_float2(tf32f(sspf(acc[j][2])), tf32f(sspf(acc[j][3])));
    }
}

// ---------------- fused edge kernel: persistent + steal + MLP-batch phase2 --
#define TE 64
#define HRS 36
#define WSS 324
__global__ void __launch_bounds__(320, 2)
edge_kernel(const int* __restrict__ ei,
            const float* __restrict__ sh,
            const float* __restrict__ h1a,
            const float* __restrict__ h1l,
            const float* __restrict__ xg,
            float* __restrict__ acc, int nE, int Etot) {
    extern __shared__ float sm[];
    float* hA  = sm;
    float* hB  = sm + 2304;
    float* ws  = sm + 4608;
    float* WlS = sm + 14976;
    float* shs = sm + 26496;
    int*   idxs = (int*)(sm + 26752);      // src[64] | dst[64] | s_next
    int*   s_next = idxs + 128;
    int tid = threadIdx.x;
    int lane = tid & 31, wrp = tid >> 5;
    int group = lane >> 2, tig = lane & 3;

    unsigned bf[4][4][2];
    #pragma unroll
    for (int j = 0; j < 4; j++) {
        int n0 = (wrp * 4 + j) * 8;
        #pragma unroll
        for (int ks = 0; ks < 4; ks++) {
            bf[j][ks][0] = __float_as_uint(g_WfT[(n0 + group) * 32 + ks * 8 + tig]);
            bf[j][ks][1] = __float_as_uint(g_WfT[(n0 + group) * 32 + ks * 8 + tig + 4]);
        }
    }
    for (int i = tid; i < 10240; i += 320) {
        int col = i >> 5, k = i & 31;
        WlS[col * 36 + k] = g_WlT[col * 32 + k];
    }

    unsigned hA_s = (unsigned)__cvta_generic_to_shared(hA);
    unsigned hB_s = (unsigned)__cvta_generic_to_shared(hB);

    const float PW_S = 0.44721359549995793f;
    const float PW_V = 0.77459666924148337f;
    const float IS3  = 0.57735026918962576f;
    const float IS2  = 0.70710678118654752f;

    int t = tid - 256;
    int psrc = 0, pdst = -1;
    float4 psh = make_float4(0.f, 0.f, 0.f, 0.f);

    int ntiles = (nE + TE - 1) / TE;
    int tile = blockIdx.x;
    {   // prologue prefetch for the statically-assigned first tile
        int e0 = tile * TE;
        if (t >= 0) {
            int e = e0 + t;
            bool v = (e < nE);
            pdst = v ? ei[e] : -1;
            psrc = v ? ei[Etot + e] : 0;
            psh  = v ? *(const float4*)&sh[e * 4] : make_float4(0.f, 0.f, 0.f, 0.f);
            const float* sa = h1a + (v ? e : 0) * 32;
            const float* sb = h1l + (v ? e : 0) * 32;
            int sz = v ? 16 : 0;
            #pragma unroll
            for (int c = 0; c < 8; c++) {
                cpa16(hA_s + t * 144 + c * 16, sa + c * 4, sz);
                cpa16(hB_s + t * 144 + c * 16, sb + c * 4, sz);
            }
        }
        asm volatile("cp.async.commit_group;" ::: "memory");
    }

    while (tile < ntiles) {
        if (t >= 0) {
            idxs[t]      = psrc;
            idxs[64 + t] = pdst;
            ((float4*)shs)[t] = psh;
        }
        if (tid == 0) *s_next = atomicAdd(&g_tilectr, 1);   // steal next tile
        asm volatile("cp.async.wait_group 0;" ::: "memory");
        __syncthreads();
        int next = *s_next;

        #pragma unroll 1
        for (int half = 0; half < 2; half++) {
            #pragma unroll 1
            for (int mm = 0; mm < 2; mm++) {
                int m0 = (half * 2 + mm) * 16;
                int rowA = (m0 + group) * HRS;
                float dA[4][4] = {}, dB[4][4] = {};
                #pragma unroll
                for (int ks = 0; ks < 4; ks++) {
                    int c = ks * 8 + tig;
                    unsigned aA[4], aB[4];
                    aA[0] = __float_as_uint(hA[rowA + c]);
                    aA[1] = __float_as_uint(hA[rowA + 8 * HRS + c]);
                    aA[2] = __float_as_uint(hA[rowA + c + 4]);
                    aA[3] = __float_as_uint(hA[rowA + 8 * HRS + c + 4]);
                    aB[0] = __float_as_uint(hB[rowA + c]);
                    aB[1] = __float_as_uint(hB[rowA + 8 * HRS + c]);
                    aB[2] = __float_as_uint(hB[rowA + c + 4]);
                    aB[3] = __float_as_uint(hB[rowA + 8 * HRS + c + 4]);
                    #pragma unroll
                    for (int j = 0; j < 4; j++) {
                        mma_tf32(dA[j], aA, bf[j][ks]);
                        unsigned bl[2];
                        int br = ((wrp * 4 + j) * 8 + group) * 36 + ks * 8 + tig;
                        bl[0] = __float_as_uint(WlS[br]);
                        bl[1] = __float_as_uint(WlS[br + 4]);
                        mma_tf32(dB[j], aB, bl);
                    }
                }
                int lrow = mm * 16 + group;
                #pragma unroll
                for (int j = 0; j < 4; j++) {
                    int col0 = (wrp * 4 + j) * 8 + 2 * tig;
                    *(float2*)&ws[lrow * WSS + col0] =
                        make_float2(dA[j][0] * dB[j][0], dA[j][1] * dB[j][1]);
                    *(float2*)&ws[(lrow + 8) * WSS + col0] =
                        make_float2(dA[j][2] * dB[j][2], dA[j][3] * dB[j][3]);
                }
            }
            __syncthreads();
            if (half == 1) {
                if (t >= 0 && next < ntiles) {
                    int e = next * TE + t;
                    bool v = (e < nE);
                    pdst = v ? ei[e] : -1;
                    psrc = v ? ei[Etot + e] : 0;
                    psh  = v ? *(const float4*)&sh[e * 4] : make_float4(0.f, 0.f, 0.f, 0.f);
                    const float* sa = h1a + (v ? e : 0) * 32;
                    const float* sb = h1l + (v ? e : 0) * 32;
                    int sz = v ? 16 : 0;
                    #pragma unroll
                    for (int c = 0; c < 8; c++) {
                        cpa16(hA_s + t * 144 + c * 16, sa + c * 4, sz);
                        cpa16(hB_s + t * 144 + c * 16, sb + c * 4, sz);
                    }
                }
                asm volatile("cp.async.commit_group;" ::: "memory");
            }
            // ---- phase 2: all 320 threads, groups [7,7,7,7,4], MLP batch ----
            {
                int u = tid & 63, grp = tid >> 6;          // 5 groups of 64
                int ecount = (grp < 4) ? 7 : 4;
                int ebase = half * 32 + ((grp < 4) ? grp * 7 : 28);
                int ds[7], ss[7];
                #pragma unroll
                for (int e2 = 0; e2 < 7; e2++) {
                    int el = ebase + e2;
                    bool ok = (e2 < ecount);
                    ds[e2] = ok ? idxs[64 + el] : -1;
                    ss[e2] = ok ? idxs[el] : 0;
                }
                float4 q[7];
                #pragma unroll
                for (int e2 = 0; e2 < 7; e2++) {
                    int s = (ds[e2] >= 0) ? ss[e2] : 0;
                    q[e2] = *(const float4*)&xg[s * 256 + u * 4];
                }
                #pragma unroll
                for (int e2 = 0; e2 < 7; e2++) {
                    int d = ds[e2];
                    if (d < 0) continue;
                    int el = ebase + e2;
                    float es = q[e2].x, ev0 = q[e2].y, ev1 = q[e2].z, ev2 = q[e2].w;
                    float4 shq = ((const float4*)shs)[el];
                    float s0 = shq.x, s1 = shq.y, s2 = shq.z, s3 = shq.w;
                    const float* we = ws + (el - half * 32) * WSS;
                    float w0 = we[u], w1 = we[64 + u], w2 = we[128 + u];
                    float w3 = we[192 + u], w4 = we[256 + u];
                    float dotv = ev0 * s1 + ev1 * s2 + ev2 * s3;
                    float c0 = ev1 * s3 - ev2 * s2;
                    float c1 = ev2 * s1 - ev0 * s3;
                    float c2 = ev0 * s2 - ev1 * s1;
                    float outs = PW_S * (w0 * es * s0 + w3 * dotv * IS3);
                    float k2 = PW_V * w2 * s0;
                    float k4 = PW_V * w4 * IS2;
                    float k1 = PW_V * w1 * es;
                    float o0 = k1 * s1 + k2 * ev0 + k4 * c0;
                    float o1 = k1 * s2 + k2 * ev1 + k4 * c1;
                    float o2 = k1 * s3 + k2 * ev2 + k4 * c2;
                    float* pa = acc + d * 256 + u * 4;
                    asm volatile("red.global.add.v4.f32 [%0], {%1, %2, %3, %4};"
                                 :: "l"(pa), "f"(outs), "f"(o0), "f"(o1), "f"(o2) : "memory");
                }
            }
            __syncthreads();
        }
        tile = next;
    }
}

// ---------------- launch ----------------------------------------------------
extern "C" void kernel_launch(void* const* d_in, const int* in_sizes, int n_in,
                              void* d_out, int out_size) {
    const float* x     = (const float*)d_in[0];
    const int*   ei    = (const int*)  d_in[1];
    const float* sh    = (const float*)d_in[2];
    const float* attr  = (const float*)d_in[3];
    const float* Wpre0 = (const float*)d_in[4];
    const float* bpre0 = (const float*)d_in[5];
    const float* Wpre1 = (const float*)d_in[6];
    const float* Wg1   = (const float*)d_in[7];
    const float* bg1   = (const float*)d_in[8];
    const float* Wg2   = (const float*)d_in[9];
    const float* bg2   = (const float*)d_in[10];
    const float* Wn0   = (const float*)d_in[11];
    const float* bn0   = (const float*)d_in[12];
    const float* Wn1   = (const float*)d_in[13];
    const float* Wf1   = (const float*)d_in[14];
    const float* Wf2   = (const float*)d_in[15];
    const float* Wl1   = (const float*)d_in[16];
    const float* Wl2   = (const float*)d_in[17];
    const float* Wo0   = (const float*)d_in[18];
    const float* bo0   = (const float*)d_in[19];
    const float* Wo1   = (const float*)d_in[20];

    int N = in_sizes[0] / 256;
    int E = in_sizes[1] / 2;

    float *pre, *tmp, *xgp, *accp, *h1a, *h1l;
    cudaGetSymbolAddress((void**)&pre,  g_pre);
    cudaGetSymbolAddress((void**)&tmp,  g_tmp);
    cudaGetSymbolAddress((void**)&xgp,  g_xg);
    cudaGetSymbolAddress((void**)&accp, g_acc);
    cudaGetSymbolAddress((void**)&h1a,  g_h1a);
    cudaGetSymbolAddress((void**)&h1l,  g_h1l);

    static const int E3_SMEM   = (8192 + 4096 + 64) * 4;
    static const int GATE_SMEM = (16384 * 2 + 8704 * 2) * 4;
    static const int H1A_SMEM  = (8704 + 2304) * 4;
    static const int H1L_SMEM  = (16896 + 4352 + 256) * 4;
    static const int EDGE_SMEM = (2304 * 2 + 10368 + 11520 + 256 + 132) * 4;
    cudaFuncSetAttribute(e3_kernel<0,1,1>, cudaFuncAttributeMaxDynamicSharedMemorySize, E3_SMEM);
    cudaFuncSetAttribute(e3_kernel<1,1,1>, cudaFuncAttributeMaxDynamicSharedMemorySize, E3_SMEM);
    cudaFuncSetAttribute(e3_kernel<1,0,0>, cudaFuncAttributeMaxDynamicSharedMemorySize, E3_SMEM);
    cudaFuncSetAttribute(gate_kernel, cudaFuncAttributeMaxDynamicSharedMemorySize, GATE_SMEM);
    cudaFuncSetAttribute(h1a_mma,  cudaFuncAttributeMaxDynamicSharedMemorySize, H1A_SMEM);
    cudaFuncSetAttribute(h1l_mma,  cudaFuncAttributeMaxDynamicSharedMemorySize, H1L_SMEM);
    cudaFuncSetAttribute(edge_kernel, cudaFuncAttributeMaxDynamicSharedMemorySize, EDGE_SMEM);

    static cudaStream_t s1 = nullptr, s2 = nullptr;
    static cudaEvent_t ev0, evP, ev1, ev2;
    if (!s1) {
        cudaStreamCreateWithFlags(&s1, cudaStreamNonBlocking);
        cudaStreamCreateWithFlags(&s2, cudaStreamNonBlocking);
        cudaEventCreateWithFlags(&ev0, cudaEventDisableTiming);
        cudaEventCreateWithFlags(&evP, cudaEventDisableTiming);
        cudaEventCreateWithFlags(&ev1, cudaEventDisableTiming);
        cudaEventCreateWithFlags(&ev2, cudaEventDisableTiming);
    }
    cudaStream_t d = 0;

    cudaEventRecord(ev0, d);
    cudaStreamWaitEvent(s1, ev0, 0);
    gate_kernel<<<(N + 63) / 64, 512, GATE_SMEM, s1>>>(x, Wg1, bg1, Wg2, bg2, tmp, N);

    prep_kernel<<<48, 256, 0, d>>>(Wf2, Wl2, Wl1, Wpre0, Wpre1, Wn0, Wn1, Wo0, Wo1, Wf1);
    cudaEventRecord(evP, d);
    cudaStreamWaitEvent(s2, evP, 0);

    h1a_mma<<<(E + 127) / 128, 256, H1A_SMEM, s2>>>(attr, h1a, E);
    cudaEventRecord(ev2, s2);

    e3_kernel<0, 1, 1><<<(N + 15) / 16, 256, E3_SMEM, d>>>(x, 0, bpre0, pre, nullptr, N);
    h1l_mma<<<(E + 127) / 128, 256, H1L_SMEM, d>>>(ei, pre, h1l, E, E);

    cudaStreamWaitEvent(s1, evP, 0);
    e3_kernel<1, 1, 1><<<(N + 15) / 16, 256, E3_SMEM, s1>>>(tmp, 1, bn0, xgp, accp, N);
    cudaEventRecord(ev1, s1);

    cudaStreamWaitEvent(d, ev1, 0);
    cudaStreamWaitEvent(d, ev2, 0);
    int ntiles = (E + TE - 1) / TE;
    int eblocks = ntiles < EDGE_BLOCKS ? ntiles : EDGE_BLOCKS;
    edge_kernel<<<eblocks, 320, EDGE_SMEM, d>>>(ei, sh, h1a, h1l, xgp, accp, E, E);
    e3_kernel<1, 0, 0><<<(N + 15) / 16, 256, E3_SMEM, d>>>(accp, 2, bo0, (float*)d_out, nullptr, N);
}

// round 17
// speedup vs baseline: 1.1465x; 1.0387x over previous
#include <cuda_runtime.h>
#include <math.h>

#define MAXN 20000
#define MAXE 320000

typedef unsigned long long ull;
typedef ulonglong2 ull2;

// ---------------- scratch (device globals) ---------------------------------
__device__ float g_pre[MAXN * 256];
__device__ float g_tmp[MAXN * 256];
__device__ float g_xg [MAXN * 256];
__device__ float g_acc[MAXN * 256];
__device__ float g_h1a[MAXE * 32];
__device__ float g_h1l[MAXE * 32];
__device__ float g_WfT[320 * 32];
__device__ float g_WlT[320 * 32];
__device__ float g_Wf1T[32 * 72];
__device__ float g_Wl1T[32 * 136];
__device__ ull   g_eW[3 * 4096];
__device__ int   g_tilectr;

__device__ __forceinline__ float sspf(float x) {
    float sp = (x > 15.f) ? x : log1pf(expf(x));
    return sp - 0.69314718055994531f;
}
__device__ __forceinline__ float siluf(float x) {
    return x / (1.f + expf(-x));
}
__device__ __forceinline__ ull pack2(float a, float b) {
    ull r; asm("mov.b64 %0, {%1, %2};" : "=l"(r) : "f"(a), "f"(b)); return r;
}
__device__ __forceinline__ void fma2(ull& d, ull a, ull b) {
    asm("fma.rn.f32x2 %0, %1, %2, %0;" : "+l"(d) : "l"(a), "l"(b));
}
__device__ __forceinline__ void unpack2(ull v, float& lo, float& hi) {
    asm("mov.b64 {%0, %1}, %2;" : "=f"(lo), "=f"(hi) : "l"(v));
}
__device__ __forceinline__ unsigned tf32r(float x) {
    unsigned r; asm("cvt.rna.tf32.f32 %0, %1;" : "=r"(r) : "f"(x)); return r;
}
__device__ __forceinline__ float tf32f(float x) {
    return __uint_as_float(tf32r(x));
}
__device__ __forceinline__ void mma_tf32(float* d, const unsigned* a, const unsigned* b) {
    asm("mma.sync.aligned.m16n8k8.row.col.f32.tf32.tf32.f32 "
        "{%0,%1,%2,%3}, {%4,%5,%6,%7}, {%8,%9}, {%0,%1,%2,%3};"
        : "+f"(d[0]), "+f"(d[1]), "+f"(d[2]), "+f"(d[3])
        : "r"(a[0]), "r"(a[1]), "r"(a[2]), "r"(a[3]), "r"(b[0]), "r"(b[1]));
}
__device__ __forceinline__ void cpa16(unsigned dst, const float* src, int sz) {
    asm volatile("cp.async.cg.shared.global [%0], [%1], 16, %2;"
                 :: "r"(dst), "l"(src), "r"(sz) : "memory");
}

// ---------------- weight prep ----------------------------------------------
#define EDGE_BLOCKS 296
__global__ void prep_kernel(const float* __restrict__ Wf2,
                            const float* __restrict__ Wl2,
                            const float* __restrict__ Wl1,
                            const float* __restrict__ Wpre0,
                            const float* __restrict__ Wpre1,
                            const float* __restrict__ Wn0,
                            const float* __restrict__ Wn1,
                            const float* __restrict__ Wo0,
                            const float* __restrict__ Wo1,
                            const float* __restrict__ Wf1) {
    int i = blockIdx.x * 256 + threadIdx.x;
    if (i == 0) g_tilectr = EDGE_BLOCKS;
    const float is32 = 0.17677669529663687f;
    const float r192 = 0.07216878364870323f;
    if (i < 320 * 32) {
        int c = i >> 5, k = i & 31;
        g_WfT[i] = tf32f(Wf2[k * 320 + c] * is32);
        g_WlT[i] = tf32f(Wl2[k * 320 + c] * is32);
    }
    if (i < 3 * 4096) {
        int p = i >> 12, r = i & 4095;
        const float* w0 = (p == 0) ? Wpre0 : (p == 1) ? Wn0 : Wo0;
        const float* w1 = (p == 0) ? Wpre1 : (p == 1) ? Wn1 : Wo1;
        g_eW[i] = pack2(w0[r] * 0.125f, w1[r] * 0.125f);
    }
    if (i < 2048) {
        int c = i >> 6, k = i & 63;
        g_Wf1T[c * 72 + k] = tf32f(Wf1[k * 32 + c] * 0.125f);
    }
    if (i < 4096) {
        int c = i >> 7, k = i & 127;
        float v = (k < 64) ? (Wl1[k * 32 + c] + Wl1[(64 + k) * 32 + c]) * r192
                           : Wl1[(64 + k) * 32 + c] * r192;
        g_Wl1T[c * 136 + k] = tf32f(v);
    }
}

// ---------------- e3_linear: 16 nodes/block, weights via L1 (__ldg) ---------
template<int IL, int OL, int OL2>
__global__ void e3_kernel(const float* __restrict__ in,
                          int widx,
                          const float* __restrict__ b0,
                          float* __restrict__ out,
                          float* __restrict__ out2, int nN) {
    extern __shared__ float sme3[];
    float* ins = sme3;                   // 16*256 = 4096 floats
    float* b0s = sme3 + 4096;            // 64
    int tid = threadIdx.x;
    const ull* __restrict__ Wg = g_eW + widx * 4096;
    if (tid < 64) b0s[tid] = b0[tid];
    int n0 = blockIdx.x * 16;
    if (IL == 0) {
        for (int i = tid; i < 256; i += 256) {
            int nl = i >> 4, g4 = i & 15;
            int u0 = g4 * 4;
            int n = n0 + nl;
            float4 a = make_float4(0.f,0.f,0.f,0.f), b = a, cc = a, dd = a;
            if (n < nN) {
                const float* xr = in + n * 256;
                a  = *(const float4*)(xr + u0);
                const float4* vp = (const float4*)(xr + 64 + u0 * 3);
                b = vp[0]; cc = vp[1]; dd = vp[2];
            }
            float4* q = (float4*)(ins + nl * 256 + u0 * 4);
            q[0] = make_float4(a.x, b.x, b.y, b.z);
            q[1] = make_float4(a.y, b.w, cc.x, cc.y);
            q[2] = make_float4(a.z, cc.z, cc.w, dd.x);
            q[3] = make_float4(a.w, dd.y, dd.z, dd.w);
        }
    } else {
        for (int i = tid; i < 1024; i += 256) {
            int nl = i >> 6, q = i & 63;
            int n = n0 + nl;
            float4 v = (n < nN) ? ((const float4*)(in + n * 256))[q]
                                : make_float4(0.f, 0.f, 0.f, 0.f);
            ((float4*)(ins + nl * 256))[q] = v;
        }
    }
    __syncthreads();
    int v = tid & 63, g = tid >> 6;
    const float* base = ins + g * 4 * 256;
    ull acc[4][2] = {};
    #pragma unroll 4
    for (int u = 0; u < 64; u++) {
        ull wp = __ldg(&Wg[u * 64 + v]);
        float w0, w1; unpack2(wp, w0, w1);
        ull wq = pack2(w1, w1);
        #pragma unroll
        for (int t = 0; t < 4; t++) {
            ull2 q = *(const ull2*)(base + t * 256 + u * 4);
            fma2(acc[t][0], wp, q.x);
            fma2(acc[t][1], wq, q.y);
        }
    }
    float bias = b0s[v];
    float rs[4], r0[4], r1[4], r2[4];
    #pragma unroll
    for (int t = 0; t < 4; t++) {
        unpack2(acc[t][0], rs[t], r0[t]);
        unpack2(acc[t][1], r1[t], r2[t]);
        rs[t] += bias;
    }
    #pragma unroll
    for (int t = 0; t < 4; t++) {
        int n = n0 + g * 4 + t;
        if (n >= nN) continue;
        float4 q = make_float4(rs[t], r0[t], r1[t], r2[t]);
        if (OL == 1) ((float4*)(out + n * 256))[v] = q;
        if (out2 && OL2 == 1) ((float4*)(out2 + n * 256))[v] = q;
    }
    if (OL == 0) {
        __syncthreads();
        #pragma unroll
        for (int t = 0; t < 4; t++) {
            float* row = ins + (g * 4 + t) * 256;
            row[v] = rs[t];
            row[64 + v * 3 + 0] = r0[t];
            row[64 + v * 3 + 1] = r1[t];
            row[64 + v * 3 + 2] = r2[t];
        }
        __syncthreads();
        for (int i = tid; i < 1024; i += 256) {
            int nl = i >> 6, q = i & 63;
            int n = n0 + nl;
            if (n < nN)
                ((float4*)(out + n * 256))[q] = ((float4*)(ins + nl * 256))[q];
        }
    }
}

// ---------------- gate MLP: PERSISTENT (weights staged once per block) ------
__global__ void __launch_bounds__(512, 1)
gate_kernel(const float* __restrict__ x,
            const float* __restrict__ Wg1,
            const float* __restrict__ bg1,
            const float* __restrict__ Wg2,
            const float* __restrict__ bg2,
            float* __restrict__ outb, int nN) {
    extern __shared__ float sm[];
    float* W1s = sm;
    float* W2s = sm + 16384;
    float* f0t = sm + 32768;
    float* hst = sm + 41472;
    int tid = threadIdx.x;
    for (int i = tid; i < 4096; i += 512) {
        ((float4*)W1s)[i] = ((const float4*)Wg1)[i];
        ((float4*)W2s)[i] = ((const float4*)Wg2)[i];
    }
    int j = tid & 127, quarter = tid >> 7;
    int nb = quarter * 16;
    float bb1 = bg1[j], bb2 = bg2[j];

    int ntiles = (nN + 63) / 64;
    for (int tile = blockIdx.x; tile < ntiles; tile += gridDim.x) {
        int n0 = tile * 64;
        __syncthreads();   // weights ready (iter 0); f0t/gbuf reads done (iter>0)
        for (int i = tid; i < 8192; i += 512) {
            int nl = i & 63, jj = i >> 6;
            int n = n0 + nl;
            float val = 0.f;
            if (n < nN) {
                const float* xr = x + n * 256;
                if (jj < 64) val = xr[jj];
                else {
                    int u = jj - 64;
                    float v0 = xr[64 + u * 3], v1 = xr[64 + u * 3 + 1], v2 = xr[64 + u * 3 + 2];
                    val = sqrtf(v0 * v0 + v1 * v1 + v2 * v2 + 1e-12f);
                }
            }
            f0t[jj * 68 + nl] = val;
        }
        __syncthreads();
        {
            ull a[8] = {};
            #pragma unroll 4
            for (int k = 0; k < 128; k++) {
                float w = W1s[k * 128 + j];
                ull wp = pack2(w, w);
                const ull2* f = (const ull2*)&f0t[k * 68 + nb];
                #pragma unroll
                for (int q = 0; q < 4; q++) {
                    ull2 v = f[q];
                    fma2(a[q * 2], wp, v.x);
                    fma2(a[q * 2 + 1], wp, v.y);
                }
            }
            #pragma unroll
            for (int q = 0; q < 8; q++) {
                float lo, hi; unpack2(a[q], lo, hi);
                hst[j * 68 + nb + q * 2]     = siluf(lo + bb1);
                hst[j * 68 + nb + q * 2 + 1] = siluf(hi + bb1);
            }
        }
        __syncthreads();
        float g[16];
        {
            ull a[8] = {};
            #pragma unroll 4
            for (int k = 0; k < 128; k++) {
                float w = W2s[k * 128 + j];
                ull wp = pack2(w, w);
                const ull2* h = (const ull2*)&hst[k * 68 + nb];
                #pragma unroll
                for (int q = 0; q < 4; q++) {
                    ull2 v = h[q];
                    fma2(a[q * 2], wp, v.x);
                    fma2(a[q * 2 + 1], wp, v.y);
                }
            }
            #pragma unroll
            for (int q = 0; q < 8; q++) {
                unpack2(a[q], g[q * 2], g[q * 2 + 1]);
                g[q * 2] += bb2; g[q * 2 + 1] += bb2;
            }
        }
        #pragma unroll
        for (int p = 0; p < 16; p++) f0t[(nb + p) * 128 + j] = g[p];
        __syncthreads();
        for (int q2 = tid; q2 < 4096; q2 += 512) {
            int nl = q2 >> 6, u = q2 & 63;
            int n = n0 + nl;
            if (n >= nN) continue;
            float gs = f0t[nl * 128 + u];
            float gv = f0t[nl * 128 + 64 + u];
            const float* xr = x + n * 256 + 64 + u * 3;
            ((float4*)(outb + n * 256))[u] = make_float4(gs, xr[0] * gv, xr[1] * gv, xr[2] * gv);
        }
    }
}

// ---------------- h1a: tf32 MMA (outputs tf32-rounded) ----------------------
__global__ void __launch_bounds__(256, 2)
h1a_mma(const float* __restrict__ attr, float* __restrict__ h1a, int nE) {
    extern __shared__ float sa[];
    float* at = sa;
    float* BT = sa + 8704;
    int tid = threadIdx.x;
    int e0 = blockIdx.x * 128;
    for (int i = tid; i < 576; i += 256)
        ((float4*)BT)[i] = ((const float4*)g_Wf1T)[i];
    for (int i = tid; i < 2048; i += 256) {
        int el = i >> 4, u0 = (i & 15) * 4;
        int e = e0 + el;
        float4 a4 = (e < nE) ? *(const float4*)&attr[e * 64 + u0]
                             : make_float4(0.f, 0.f, 0.f, 0.f);
        *(float4*)&at[el * 68 + u0] =
            make_float4(tf32f(a4.x), tf32f(a4.y), tf32f(a4.z), tf32f(a4.w));
    }
    __syncthreads();
    int lane = tid & 31, w = tid >> 5;
    int group = lane >> 2, tig = lane & 3;
    int m0 = w * 16;
    int rowA = (m0 + group) * 68;
    float acc[4][4] = {};
    #pragma unroll 1
    for (int ks = 0; ks < 8; ks++) {
        int c = ks * 8 + tig;
        unsigned a[4];
        a[0] = __float_as_uint(at[rowA + c]);
        a[1] = __float_as_uint(at[rowA + 544 + c]);
        a[2] = __float_as_uint(at[rowA + c + 4]);
        a[3] = __float_as_uint(at[rowA + 544 + c + 4]);
        #pragma unroll
        for (int j = 0; j < 4; j++) {
            unsigned b[2];
            int br = (j * 8 + group) * 72 + ks * 8 + tig;
            b[0] = __float_as_uint(BT[br]);
            b[1] = __float_as_uint(BT[br + 4]);
            mma_tf32(acc[j], a, b);
        }
    }
    int eA = e0 + m0 + group, eB = eA + 8;
    #pragma unroll
    for (int j = 0; j < 4; j++) {
        int c0 = j * 8 + 2 * tig;
        if (eA < nE)
            *(float2*)&h1a[eA * 32 + c0] =
                make_float2(tf32f(sspf(acc[j][0])), tf32f(sspf(acc[j][1])));
        if (eB < nE)
            *(float2*)&h1a[eB * 32 + c0] =
                make_float2(tf32f(sspf(acc[j][2])), tf32f(sspf(acc[j][3])));
    }
}

// ---------------- h1l: tf32 MMA (outputs tf32-rounded) ----------------------
__global__ void __launch_bounds__(256, 2)
h1l_mma(const int* __restrict__ ei, const float* __restrict__ pre,
        float* __restrict__ h1l, int nE, int Etot) {
    extern __shared__ float sl[];
    float* st = sl;
    float* BT = sl + 16896;
    int*   idx = (int*)(sl + 21248);
    int tid = threadIdx.x;
    int e0 = blockIdx.x * 128;
    for (int i = tid; i < 1088; i += 256)
        ((float4*)BT)[i] = ((const float4*)g_Wl1T)[i];
    if (tid < 128) {
        int e = e0 + tid;
        bool v = (e < nE);
        idx[tid]       = v ? ei[e] : 0;
        idx[128 + tid] = v ? ei[Etot + e] : 0;
    }
    __syncthreads();
    for (int i = tid; i < 8192; i += 256) {
        int el = i >> 6, u = i & 63;
        int d = idx[el], s = idx[128 + el];
        float4 qd = *(const float4*)&pre[d * 256 + u * 4];
        float4 qs = *(const float4*)&pre[s * 256 + u * 4];
        st[el * 132 + u] = tf32f(qd.x);
        st[el * 132 + 64 + u] =
            tf32f((qd.y * qs.y + qd.z * qs.z + qd.w * qs.w) * (1.f / 3.f));
    }
    __syncthreads();
    int lane = tid & 31, w = tid >> 5;
    int group = lane >> 2, tig = lane & 3;
    int m0 = w * 16;
    int rowA = (m0 + group) * 132;
    float acc[4][4] = {};
    #pragma unroll 1
    for (int ks = 0; ks < 16; ks++) {
        int c = ks * 8 + tig;
        unsigned a[4];
        a[0] = __float_as_uint(st[rowA + c]);
        a[1] = __float_as_uint(st[rowA + 1056 + c]);
        a[2] = __float_as_uint(st[rowA + c + 4]);
        a[3] = __float_as_uint(st[rowA + 1056 + c + 4]);
        #pragma unroll
        for (int j = 0; j < 4; j++) {
            unsigned b[2];
            int br = (j * 8 + group) * 136 + ks * 8 + tig;
            b[0] = __float_as_uint(BT[br]);
            b[1] = __float_as_uint(BT[br + 4]);
            mma_tf32(acc[j], a, b);
        }
    }
    int eA = e0 + m0 + group, eB = eA + 8;
    #pragma unroll
    for (int j = 0; j < 4; j++) {
        int c0 = j * 8 + 2 * tig;
        if (eA < nE)
            *(float2*)&h1l[eA * 32 + c0] =
                make_float2(tf32f(sspf(acc[j][0])), tf32f(sspf(acc[j][1])));
        if (eB < nE)
            *(float2*)&h1l[eB * 32 + c0] =
                make_float2(tf32f(sspf(acc[j][2])), tf32f(sspf(acc[j][3])));
    }
}

// ---------------- fused edge kernel: persistent + steal + MLP-batch phase2 --
#define TE 64
#define HRS 36
#define WSS 324
__global__ void __launch_bounds__(320, 2)
edge_kernel(const int* __restrict__ ei,
            const float* __restrict__ sh,
            const float* __restrict__ h1a,
            const float* __restrict__ h1l,
            const float* __restrict__ xg,
            float* __restrict__ acc, int nE, int Etot) {
    extern __shared__ float sm[];
    float* hA  = sm;
    float* hB  = sm + 2304;
    float* ws  = sm + 4608;
    float* WlS = sm + 14976;
    float* shs = sm + 26496;
    int*   idxs = (int*)(sm + 26752);
    int*   s_next = idxs + 128;
    int tid = threadIdx.x;
    int lane = tid & 31, wrp = tid >> 5;
    int group = lane >> 2, tig = lane & 3;

    unsigned bf[4][4][2];
    #pragma unroll
    for (int j = 0; j < 4; j++) {
        int n0 = (wrp * 4 + j) * 8;
        #pragma unroll
        for (int ks = 0; ks < 4; ks++) {
            bf[j][ks][0] = __float_as_uint(g_WfT[(n0 + group) * 32 + ks * 8 + tig]);
            bf[j][ks][1] = __float_as_uint(g_WfT[(n0 + group) * 32 + ks * 8 + tig + 4]);
        }
    }
    for (int i = tid; i < 10240; i += 320) {
        int col = i >> 5, k = i & 31;
        WlS[col * 36 + k] = g_WlT[col * 32 + k];
    }

    unsigned hA_s = (unsigned)__cvta_generic_to_shared(hA);
    unsigned hB_s = (unsigned)__cvta_generic_to_shared(hB);

    const float PW_S = 0.44721359549995793f;
    const float PW_V = 0.77459666924148337f;
    const float IS3  = 0.57735026918962576f;
    const float IS2  = 0.70710678118654752f;

    int t = tid - 256;
    int psrc = 0, pdst = -1;
    float4 psh = make_float4(0.f, 0.f, 0.f, 0.f);

    int ntiles = (nE + TE - 1) / TE;
    int tile = blockIdx.x;
    {
        int e0 = tile * TE;
        if (t >= 0) {
            int e = e0 + t;
            bool v = (e < nE);
            pdst = v ? ei[e] : -1;
            psrc = v ? ei[Etot + e] : 0;
            psh  = v ? *(const float4*)&sh[e * 4] : make_float4(0.f, 0.f, 0.f, 0.f);
            const float* sa = h1a + (v ? e : 0) * 32;
            const float* sb = h1l + (v ? e : 0) * 32;
            int sz = v ? 16 : 0;
            #pragma unroll
            for (int c = 0; c < 8; c++) {
                cpa16(hA_s + t * 144 + c * 16, sa + c * 4, sz);
                cpa16(hB_s + t * 144 + c * 16, sb + c * 4, sz);
            }
        }
        asm volatile("cp.async.commit_group;" ::: "memory");
    }

    while (tile < ntiles) {
        if (t >= 0) {
            idxs[t]      = psrc;
            idxs[64 + t] = pdst;
            ((float4*)shs)[t] = psh;
        }
        if (tid == 0) *s_next = atomicAdd(&g_tilectr, 1);
        asm volatile("cp.async.wait_group 0;" ::: "memory");
        __syncthreads();
        int next = *s_next;

        #pragma unroll 1
        for (int half = 0; half < 2; half++) {
            #pragma unroll 1
            for (int mm = 0; mm < 2; mm++) {
                int m0 = (half * 2 + mm) * 16;
                int rowA = (m0 + group) * HRS;
                float dA[4][4] = {}, dB[4][4] = {};
                #pragma unroll
                for (int ks = 0; ks < 4; ks++) {
                    int c = ks * 8 + tig;
                    unsigned aA[4], aB[4];
                    aA[0] = __float_as_uint(hA[rowA + c]);
                    aA[1] = __float_as_uint(hA[rowA + 8 * HRS + c]);
                    aA[2] = __float_as_uint(hA[rowA + c + 4]);
                    aA[3] = __float_as_uint(hA[rowA + 8 * HRS + c + 4]);
                    aB[0] = __float_as_uint(hB[rowA + c]);
                    aB[1] = __float_as_uint(hB[rowA + 8 * HRS + c]);
                    aB[2] = __float_as_uint(hB[rowA + c + 4]);
                    aB[3] = __float_as_uint(hB[rowA + 8 * HRS + c + 4]);
                    #pragma unroll
                    for (int j = 0; j < 4; j++) {
                        mma_tf32(dA[j], aA, bf[j][ks]);
                        unsigned bl[2];
                        int br = ((wrp * 4 + j) * 8 + group) * 36 + ks * 8 + tig;
                        bl[0] = __float_as_uint(WlS[br]);
                        bl[1] = __float_as_uint(WlS[br + 4]);
                        mma_tf32(dB[j], aB, bl);
                    }
                }
                int lrow = mm * 16 + group;
                #pragma unroll
                for (int j = 0; j < 4; j++) {
                    int col0 = (wrp * 4 + j) * 8 + 2 * tig;
                    *(float2*)&ws[lrow * WSS + col0] =
                        make_float2(dA[j][0] * dB[j][0], dA[j][1] * dB[j][1]);
                    *(float2*)&ws[(lrow + 8) * WSS + col0] =
                        make_float2(dA[j][2] * dB[j][2], dA[j][3] * dB[j][3]);
                }
            }
            __syncthreads();
            if (half == 1) {
                if (t >= 0 && next < ntiles) {
                    int e = next * TE + t;
                    bool v = (e < nE);
                    pdst = v ? ei[e] : -1;
                    psrc = v ? ei[Etot + e] : 0;
                    psh  = v ? *(const float4*)&sh[e * 4] : make_float4(0.f, 0.f, 0.f, 0.f);
                    const float* sa = h1a + (v ? e : 0) * 32;
                    const float* sb = h1l + (v ? e : 0) * 32;
                    int sz = v ? 16 : 0;
                    #pragma unroll
                    for (int c = 0; c < 8; c++) {
                        cpa16(hA_s + t * 144 + c * 16, sa + c * 4, sz);
                        cpa16(hB_s + t * 144 + c * 16, sb + c * 4, sz);
                    }
                }
                asm volatile("cp.async.commit_group;" ::: "memory");
            }
            {
                int u = tid & 63, grp = tid >> 6;
                int ecount = (grp < 4) ? 7 : 4;
                int ebase = half * 32 + ((grp < 4) ? grp * 7 : 28);
                int ds[7], ss[7];
                #pragma unroll
                for (int e2 = 0; e2 < 7; e2++) {
                    int el = ebase + e2;
                    bool ok = (e2 < ecount);
                    ds[e2] = ok ? idxs[64 + el] : -1;
                    ss[e2] = ok ? idxs[el] : 0;
                }
                float4 q[7];
                #pragma unroll
                for (int e2 = 0; e2 < 7; e2++) {
                    int s = (ds[e2] >= 0) ? ss[e2] : 0;
                    q[e2] = *(const float4*)&xg[s * 256 + u * 4];
                }
                #pragma unroll
                for (int e2 = 0; e2 < 7; e2++) {
                    int d = ds[e2];
                    if (d < 0) continue;
                    int el = ebase + e2;
                    float es = q[e2].x, ev0 = q[e2].y, ev1 = q[e2].z, ev2 = q[e2].w;
                    float4 shq = ((const float4*)shs)[el];
                    float s0 = shq.x, s1 = shq.y, s2 = shq.z, s3 = shq.w;
                    const float* we = ws + (el - half * 32) * WSS;
                    float w0 = we[u], w1 = we[64 + u], w2 = we[128 + u];
                    float w3 = we[192 + u], w4 = we[256 + u];
                    float dotv = ev0 * s1 + ev1 * s2 + ev2 * s3;
                    float c0 = ev1 * s3 - ev2 * s2;
                    float c1 = ev2 * s1 - ev0 * s3;
                    float c2 = ev0 * s2 - ev1 * s1;
                    float outs = PW_S * (w0 * es * s0 + w3 * dotv * IS3);
                    float k2 = PW_V * w2 * s0;
                    float k4 = PW_V * w4 * IS2;
                    float k1 = PW_V * w1 * es;
                    float o0 = k1 * s1 + k2 * ev0 + k4 * c0;
                    float o1 = k1 * s2 + k2 * ev1 + k4 * c1;
                    float o2 = k1 * s3 + k2 * ev2 + k4 * c2;
                    float* pa = acc + d * 256 + u * 4;
                    asm volatile("red.global.add.v4.f32 [%0], {%1, %2, %3, %4};"
                                 :: "l"(pa), "f"(outs), "f"(o0), "f"(o1), "f"(o2) : "memory");
                }
            }
            __syncthreads();
        }
        tile = next;
    }
}

// ---------------- launch ----------------------------------------------------
extern "C" void kernel_launch(void* const* d_in, const int* in_sizes, int n_in,
                              void* d_out, int out_size) {
    const float* x     = (const float*)d_in[0];
    const int*   ei    = (const int*)  d_in[1];
    const float* sh    = (const float*)d_in[2];
    const float* attr  = (const float*)d_in[3];
    const float* Wpre0 = (const float*)d_in[4];
    const float* bpre0 = (const float*)d_in[5];
    const float* Wpre1 = (const float*)d_in[6];
    const float* Wg1   = (const float*)d_in[7];
    const float* bg1   = (const float*)d_in[8];
    const float* Wg2   = (const float*)d_in[9];
    const float* bg2   = (const float*)d_in[10];
    const float* Wn0   = (const float*)d_in[11];
    const float* bn0   = (const float*)d_in[12];
    const float* Wn1   = (const float*)d_in[13];
    const float* Wf1   = (const float*)d_in[14];
    const float* Wf2   = (const float*)d_in[15];
    const float* Wl1   = (const float*)d_in[16];
    const float* Wl2   = (const float*)d_in[17];
    const float* Wo0   = (const float*)d_in[18];
    const float* bo0   = (const float*)d_in[19];
    const float* Wo1   = (const float*)d_in[20];

    int N = in_sizes[0] / 256;
    int E = in_sizes[1] / 2;

    float *pre, *tmp, *xgp, *accp, *h1a, *h1l;
    cudaGetSymbolAddress((void**)&pre,  g_pre);
    cudaGetSymbolAddress((void**)&tmp,  g_tmp);
    cudaGetSymbolAddress((void**)&xgp,  g_xg);
    cudaGetSymbolAddress((void**)&accp, g_acc);
    cudaGetSymbolAddress((void**)&h1a,  g_h1a);
    cudaGetSymbolAddress((void**)&h1l,  g_h1l);

    static const int E3_SMEM   = (4096 + 64) * 4;                  // 16.6 KB
    static const int GATE_SMEM = (16384 * 2 + 8704 * 2) * 4;
    static const int H1A_SMEM  = (8704 + 2304) * 4;
    static const int H1L_SMEM  = (16896 + 4352 + 256) * 4;
    static const int EDGE_SMEM = (2304 * 2 + 10368 + 11520 + 256 + 132) * 4;
    cudaFuncSetAttribute(e3_kernel<0,1,1>, cudaFuncAttributeMaxDynamicSharedMemorySize, E3_SMEM);
    cudaFuncSetAttribute(e3_kernel<1,1,1>, cudaFuncAttributeMaxDynamicSharedMemorySize, E3_SMEM);
    cudaFuncSetAttribute(e3_kernel<1,0,0>, cudaFuncAttributeMaxDynamicSharedMemorySize, E3_SMEM);
    cudaFuncSetAttribute(gate_kernel, cudaFuncAttributeMaxDynamicSharedMemorySize, GATE_SMEM);
    cudaFuncSetAttribute(h1a_mma,  cudaFuncAttributeMaxDynamicSharedMemorySize, H1A_SMEM);
    cudaFuncSetAttribute(h1l_mma,  cudaFuncAttributeMaxDynamicSharedMemorySize, H1L_SMEM);
    cudaFuncSetAttribute(edge_kernel, cudaFuncAttributeMaxDynamicSharedMemorySize, EDGE_SMEM);

    static cudaStream_t s1 = nullptr, s2 = nullptr;
    static cudaEvent_t ev0, evP, ev1, ev2;
    if (!s1) {
        cudaStreamCreateWithFlags(&s1, cudaStreamNonBlocking);
        cudaStreamCreateWithFlags(&s2, cudaStreamNonBlocking);
        cudaEventCreateWithFlags(&ev0, cudaEventDisableTiming);
        cudaEventCreateWithFlags(&evP, cudaEventDisableTiming);
        cudaEventCreateWithFlags(&ev1, cudaEventDisableTiming);
        cudaEventCreateWithFlags(&ev2, cudaEventDisableTiming);
    }
    cudaStream_t d = 0;

    cudaEventRecord(ev0, d);
    cudaStreamWaitEvent(s1, ev0, 0);
    int gate_blocks = (N + 63) / 64;
    if (gate_blocks > 148) gate_blocks = 148;
    gate_kernel<<<gate_blocks, 512, GATE_SMEM, s1>>>(x, Wg1, bg1, Wg2, bg2, tmp, N);

    prep_kernel<<<48, 256, 0, d>>>(Wf2, Wl2, Wl1, Wpre0, Wpre1, Wn0, Wn1, Wo0, Wo1, Wf1);
    cudaEventRecord(evP, d);
    cudaStreamWaitEvent(s2, evP, 0);

    h1a_mma<<<(E + 127) / 128, 256, H1A_SMEM, s2>>>(attr, h1a, E);
    cudaEventRecord(ev2, s2);

    e3_kernel<0, 1, 1><<<(N + 15) / 16, 256, E3_SMEM, d>>>(x, 0, bpre0, pre, nullptr, N);
    h1l_mma<<<(E + 127) / 128, 256, H1L_SMEM, d>>>(ei, pre, h1l, E, E);

    cudaStreamWaitEvent(s1, evP, 0);
    e3_kernel<1, 1, 1><<<(N + 15) / 16, 256, E3_SMEM, s1>>>(tmp, 1, bn0, xgp, accp, N);
    cudaEventRecord(ev1, s1);

    cudaStreamWaitEvent(d, ev1, 0);
    cudaStreamWaitEvent(d, ev2, 0);
    int ntiles = (E + TE - 1) / TE;
    int eblocks = ntiles < EDGE_BLOCKS ? ntiles : EDGE_BLOCKS;
    edge_kernel<<<eblocks, 320, EDGE_SMEM, d>>>(ei, sh, h1a, h1l, xgp, accp, E, E);
    e3_kernel<1, 0, 0><<<(N + 15) / 16, 256, E3_SMEM, d>>>(accp, 2, bo0, (float*)d_out, nullptr, N);
}